// round 11
// baseline (speedup 1.0000x reference)
#include <cuda_runtime.h>
#include <cuda_fp16.h>
#include <stdint.h>

#define PP 20
#define VPW 4          // voxels per warp
#define WARPS 2
#define THREADS 64

// precomputed by lef_prep: B fragments (BN-scale folded, permuted, fp16 hi/lo)
// layout: [h(2)][lane(32)][ 16 x hi | 16 x lo ]   (idx = (nt*2+ks)*2+pair)
__device__ uint32_t g_Btab[2 * 32 * 32];
__device__ __align__(16) float g_shift[64];

__device__ __forceinline__ float sqrt_apx(float x) {
    float r; asm("sqrt.approx.f32 %0,%1;" : "=f"(r) : "f"(x)); return r;
}
__device__ __forceinline__ uint32_t pack_h2(float x, float y) {
    __half2 t = __floats2half2_rn(x, y);
    return *(uint32_t*)&t;
}
__device__ __forceinline__ uint32_t pack_hres2(float x, float y, uint32_t hipack) {
    __half2 h = *(__half2*)&hipack;
    return pack_h2(x - __half2float(h.x), y - __half2float(h.y));
}
__device__ __forceinline__ void mma16816(float* c, const uint32_t* a, const uint32_t* b) {
    asm volatile("mma.sync.aligned.m16n8k16.row.col.f32.f16.f16.f32 "
        "{%0,%1,%2,%3},{%4,%5,%6,%7},{%8,%9},{%0,%1,%2,%3};"
        : "+f"(c[0]), "+f"(c[1]), "+f"(c[2]), "+f"(c[3])
        : "r"(a[0]), "r"(a[1]), "r"(a[2]), "r"(a[3]), "r"(b[0]), "r"(b[1]));
}
// permuted W lookup: k<20 -> dist weight row 7+k ; 20..26 -> node row k-20 ; else 0
__device__ __forceinline__ float wval(const float* __restrict__ W, int k, int n) {
    if (k < 20) return W[(7 + k) * 64 + n];
    if (k < 27) return W[(k - 20) * 64 + n];
    return 0.0f;
}

// x-entry for (point with coords a / mask pm / voxel coord set cb / np), channel k
__device__ __forceinline__ float xval(const float4* cb, int np, float pm,
                                      float m0, float m1, float m2,
                                      const float4 a, int k) {
    if (k < 20) {                       // distance to point q=k, masked by q<np
        const float4 b = cb[k];
        const float dx = a.x - b.x, dy = a.y - b.y, dz = a.z - b.z;
        float d2 = dx * dx; d2 = fmaf(dy, dy, d2); d2 = fmaf(dz, dz, d2);
        return (d2 > 0.0f && k < np) ? sqrt_apx(d2) : 0.0f;
    }
    if (k >= 27) return 0.0f;
    const int c = k - 20;               // node channels, masked by p<np (pm)
    float v;
    if      (c == 0) v = a.x;
    else if (c == 1) v = a.y;
    else if (c == 2) v = a.z;
    else if (c == 3) v = a.w;
    else if (c == 4) v = a.x - m0;
    else if (c == 5) v = a.y - m1;
    else             v = a.z - m2;
    return v * pm;
}

// ---- pre-kernel: build B fragment table (fp16 hi/lo, scale-folded) + shift ----
__global__ void lef_prep(const float* __restrict__ W, const float* __restrict__ gamma_,
                         const float* __restrict__ beta_, const float* __restrict__ rmean,
                         const float* __restrict__ rvar)
{
    const int t = threadIdx.x;                    // 64 threads
    {
        const float s = gamma_[t] * rsqrtf(rvar[t] + 1e-3f);
        g_shift[t] = beta_[t] - rmean[t] * s;
    }
    const int h = t >> 5, lane = t & 31, t4 = lane & 3, gg = lane >> 2;
    uint32_t vals[32];
    #pragma unroll
    for (int nt = 0; nt < 4; ++nt) {
        const int nn = h * 32 + nt * 8 + gg;
        const float s = gamma_[nn] * rsqrtf(rvar[nn] + 1e-3f);
        #pragma unroll
        for (int ks = 0; ks < 2; ++ks) {
            const int k0 = ks * 16 + 2 * t4;
            const float w00 = wval(W, k0,     nn) * s;
            const float w01 = wval(W, k0 + 1, nn) * s;
            const float w10 = wval(W, k0 + 8, nn) * s;
            const float w11 = wval(W, k0 + 9, nn) * s;
            const uint32_t h0 = pack_h2(w00, w01);
            const uint32_t h1 = pack_h2(w10, w11);
            vals[(nt * 2 + ks) * 2 + 0] = h0;
            vals[(nt * 2 + ks) * 2 + 1] = h1;
            vals[16 + (nt * 2 + ks) * 2 + 0] = pack_hres2(w00, w01, h0);
            vals[16 + (nt * 2 + ks) * 2 + 1] = pack_hres2(w10, w11, h1);
        }
    }
    uint32_t* dst = &g_Btab[(h * 32 + lane) * 32];
    #pragma unroll
    for (int i = 0; i < 32; ++i) dst[i] = vals[i];
}

__global__ void __launch_bounds__(THREADS, 8) lef_mma7_kernel(
    const float4* __restrict__ feats4,
    const int*    __restrict__ num_points,
    float* __restrict__ out,
    int V)
{
    __shared__ float4 cs4s[WARPS * VPW][PP];
    __shared__ float  meanv[WARPS * VPW][3];
    __shared__ int    npvs[WARPS * VPW];

    const int tid  = threadIdx.x;
    const int warp = tid >> 5;
    const int lane = tid & 31;
    const int t4 = lane & 3, g = lane >> 2;

    // ---- stage features (coalesced LDG.128) ----
    const int v0 = (blockIdx.x * WARPS + warp) * VPW;
    for (int t = lane; t < VPW * PP; t += 32) {
        const int vi = t / PP, p = t - vi * PP;
        const int vv = v0 + vi;
        float4 f = make_float4(0.f, 0.f, 0.f, 0.f);
        if (vv < V) f = feats4[(size_t)v0 * PP + t];
        cs4s[warp * VPW + vi][p] = f;
    }
    if (lane < VPW) {
        const int vv = v0 + lane;
        npvs[warp * VPW + lane] = (vv < V) ? num_points[vv] : 1;
    }
    __syncwarp();

    // ---- per-voxel means (unmasked sum / npts, as reference) ----
    if (lane < 12) {
        const int vi = lane / 3, d = lane - vi * 3;
        const int sv = warp * VPW + vi;
        const float* c = (const float*)&cs4s[sv][0];
        float s = 0.0f;
        #pragma unroll
        for (int p = 0; p < PP; ++p) s += c[p * 4 + d];
        meanv[sv][d] = s / (float)npvs[sv];
    }
    __syncwarp();

    // ---- build A fragments directly in registers ----
    // tile t<4: rows = voxel t, points g / g+8
    // tile 4:   row g -> voxel g>>2, p=16+(g&3) ; row g+8 -> voxel 2+(g>>2), p=16+(g&3)
    uint32_t afr[5][2][4];
    #pragma unroll
    for (int t = 0; t < 5; ++t) {
        int vi0, p0, vi1, p1;
        if (t < 4) { vi0 = t;      p0 = g;            vi1 = t;            p1 = g + 8; }
        else       { vi0 = g >> 2; p0 = 16 + (g & 3); vi1 = 2 + (g >> 2); p1 = p0;    }
        const int sv0 = warp * VPW + vi0, sv1 = warp * VPW + vi1;
        const float4* cb0 = &cs4s[sv0][0];
        const float4* cb1 = &cs4s[sv1][0];
        const float4 A0 = cb0[p0], A1 = cb1[p1];
        const int np0 = npvs[sv0], np1 = npvs[sv1];
        const float pm0 = (p0 < np0) ? 1.0f : 0.0f;
        const float pm1 = (p1 < np1) ? 1.0f : 0.0f;
        const float m00 = meanv[sv0][0], m01 = meanv[sv0][1], m02 = meanv[sv0][2];
        const float m10 = meanv[sv1][0], m11 = meanv[sv1][1], m12 = meanv[sv1][2];

        #pragma unroll
        for (int ks = 0; ks < 2; ++ks) {
            #pragma unroll
            for (int hh = 0; hh < 2; ++hh) {
                const int k0 = 16 * ks + 8 * hh + 2 * t4;
                const float r0a = xval(cb0, np0, pm0, m00, m01, m02, A0, k0);
                const float r0b = xval(cb0, np0, pm0, m00, m01, m02, A0, k0 + 1);
                const float r1a = xval(cb1, np1, pm1, m10, m11, m12, A1, k0);
                const float r1b = xval(cb1, np1, pm1, m10, m11, m12, A1, k0 + 1);
                afr[t][ks][hh * 2 + 0] = pack_h2(r0a, r0b);
                afr[t][ks][hh * 2 + 1] = pack_h2(r1a, r1b);
            }
        }
    }

    const int vsel = g >> 2;   // tile-4 voxel owned by acc4[.][0..1]; [2..3] -> vsel+2

    // ---- two 32-column halves ----
    #pragma unroll 1
    for (int h = 0; h < 2; ++h) {
        // B fragments from precomputed table (L1-hot broadcast)
        uint32_t BH[16], BL[16];
        {
            const uint4* bt = (const uint4*)&g_Btab[(h * 32 + lane) * 32];
            #pragma unroll
            for (int i = 0; i < 4; ++i) {
                const uint4 q = bt[i];
                BH[4*i] = q.x; BH[4*i+1] = q.y; BH[4*i+2] = q.z; BH[4*i+3] = q.w;
            }
            #pragma unroll
            for (int i = 0; i < 4; ++i) {
                const uint4 q = bt[4 + i];
                BL[4*i] = q.x; BL[4*i+1] = q.y; BL[4*i+2] = q.z; BL[4*i+3] = q.w;
            }
        }
        #define BHF(nt, ks) (&BH[((nt) * 2 + (ks)) * 2])
        #define BLF(nt, ks) (&BL[((nt) * 2 + (ks)) * 2])

        // tile 4 first (leftover points p=16..19 of all 4 voxels), hold acc4
        float acc4[4][4];
        #pragma unroll
        for (int nt = 0; nt < 4; ++nt)
            acc4[nt][0] = acc4[nt][1] = acc4[nt][2] = acc4[nt][3] = 0.0f;
        #pragma unroll
        for (int ks = 0; ks < 2; ++ks)
            #pragma unroll
            for (int nt = 0; nt < 4; ++nt) {
                mma16816(acc4[nt], afr[4][ks], BHF(nt, ks));
                mma16816(acc4[nt], afr[4][ks], BLF(nt, ks));
            }

        // per-voxel tiles + lean shuffle-max epilogue
        #pragma unroll
        for (int vi = 0; vi < VPW; ++vi) {
            float acc[4][4];
            #pragma unroll
            for (int nt = 0; nt < 4; ++nt)
                acc[nt][0] = acc[nt][1] = acc[nt][2] = acc[nt][3] = 0.0f;
            #pragma unroll
            for (int ks = 0; ks < 2; ++ks)
                #pragma unroll
                for (int nt = 0; nt < 4; ++nt) {
                    mma16816(acc[nt], afr[vi][ks], BHF(nt, ks));
                    mma16816(acc[nt], afr[vi][ks], BLF(nt, ks));
                }

            // per-lane max over this voxel's rows (p 0..15), merge tile-4 rows
            float pmx[8];
            #pragma unroll
            for (int nt = 0; nt < 4; ++nt) {
                pmx[2*nt]   = fmaxf(acc[nt][0], acc[nt][2]);
                pmx[2*nt+1] = fmaxf(acc[nt][1], acc[nt][3]);
            }
            if (vsel == vi) {
                #pragma unroll
                for (int nt = 0; nt < 4; ++nt) {
                    pmx[2*nt]   = fmaxf(pmx[2*nt],   acc4[nt][0]);
                    pmx[2*nt+1] = fmaxf(pmx[2*nt+1], acc4[nt][1]);
                }
            }
            if (vsel == vi - 2) {
                #pragma unroll
                for (int nt = 0; nt < 4; ++nt) {
                    pmx[2*nt]   = fmaxf(pmx[2*nt],   acc4[nt][2]);
                    pmx[2*nt+1] = fmaxf(pmx[2*nt+1], acc4[nt][3]);
                }
            }

            // lean butterfly: drop half the values each round
            const bool b4 = (lane & 16) != 0;
            float q[4];
            #pragma unroll
            for (int i = 0; i < 4; ++i) {
                const float send = b4 ? pmx[i] : pmx[4 + i];
                const float recv = __shfl_xor_sync(0xffffffffu, send, 16);
                q[i] = fmaxf(b4 ? pmx[4 + i] : pmx[i], recv);
            }
            const bool b3 = (lane & 8) != 0;
            float r2v[2];
            #pragma unroll
            for (int i = 0; i < 2; ++i) {
                const float send = b3 ? q[i] : q[2 + i];
                const float recv = __shfl_xor_sync(0xffffffffu, send, 8);
                r2v[i] = fmaxf(b3 ? q[2 + i] : q[i], recv);
            }
            const float f0 = fmaxf(r2v[0], __shfl_xor_sync(0xffffffffu, r2v[0], 4));
            const float f1 = fmaxf(r2v[1], __shfl_xor_sync(0xffffffffu, r2v[1], 4));

            // lanes with bit2==0 store cols ntp*8 + 2*t4 (+1)
            const int vv = v0 + vi;
            if ((lane & 4) == 0 && vv < V) {
                const int ntp = (((lane >> 4) & 1) << 1) | ((lane >> 3) & 1);
                const int col = h * 32 + ntp * 8 + 2 * t4;
                const float2 sh = *(const float2*)&g_shift[col];
                float2 r2;
                r2.x = fmaxf(0.0f, f0 + sh.x);
                r2.y = fmaxf(0.0f, f1 + sh.y);
                *(float2*)&out[(size_t)vv * 64 + col] = r2;
            }
        }
        #undef BHF
        #undef BLF
    }
}

extern "C" void kernel_launch(void* const* d_in, const int* in_sizes, int n_in,
                              void* d_out, int out_size) {
    const float4* feats4     = (const float4*)d_in[0];
    const int*    num_points = (const int*)   d_in[1];
    const float*  W          = (const float*) d_in[3];
    const float*  gamma_     = (const float*) d_in[4];
    const float*  beta_      = (const float*) d_in[5];
    const float*  rmean      = (const float*) d_in[6];
    const float*  rvar       = (const float*) d_in[7];
    float* out = (float*)d_out;

    const int V = in_sizes[1];
    lef_prep<<<1, 64>>>(W, gamma_, beta_, rmean, rvar);
    const int vox_per_cta = WARPS * VPW;
    const int grid = (V + vox_per_cta - 1) / vox_per_cta;
    lef_mma7_kernel<<<grid, THREADS>>>(feats4, num_points, out, V);
}

// round 12
// speedup vs baseline: 1.5673x; 1.5673x over previous
#include <cuda_runtime.h>
#include <cuda_fp16.h>
#include <stdint.h>

#define PP 20
#define VPW 4          // voxels per warp
#define WARPS 2
#define THREADS 64
#define ROWS 80        // A rows per warp = 5 m16 tiles
#define ASTR 80        // bytes per A row (32 fp16 = 64B data + 16B pad)

// precomputed by lef_prep: B fragments (BN-scale folded, permuted, single fp16)
// layout: [h(2)][lane(32)][16]   (idx = (nt*2+ks)*2+pair)
__device__ uint32_t g_Btab[2 * 32 * 16];
__device__ __align__(16) float g_shift[64];

__device__ __forceinline__ uint32_t smem_u32(const void* p) {
    uint32_t a;
    asm("{ .reg .u64 t; cvta.to.shared.u64 t, %1; cvt.u32.u64 %0, t; }" : "=r"(a) : "l"(p));
    return a;
}
__device__ __forceinline__ float sqrt_apx(float x) {
    float r; asm("sqrt.approx.f32 %0,%1;" : "=f"(r) : "f"(x)); return r;
}
__device__ __forceinline__ uint32_t pack_h2(float x, float y) {
    __half2 t = __floats2half2_rn(x, y);
    return *(uint32_t*)&t;
}
__device__ __forceinline__ void ldmat4(uint32_t* r, uint32_t addr) {
    asm volatile("ldmatrix.sync.aligned.m8n8.x4.shared.b16 {%0,%1,%2,%3}, [%4];"
        : "=r"(r[0]), "=r"(r[1]), "=r"(r[2]), "=r"(r[3]) : "r"(addr));
}
__device__ __forceinline__ void mma16816(float* c, const uint32_t* a, const uint32_t* b) {
    asm volatile("mma.sync.aligned.m16n8k16.row.col.f32.f16.f16.f32 "
        "{%0,%1,%2,%3},{%4,%5,%6,%7},{%8,%9},{%0,%1,%2,%3};"
        : "+f"(c[0]), "+f"(c[1]), "+f"(c[2]), "+f"(c[3])
        : "r"(a[0]), "r"(a[1]), "r"(a[2]), "r"(a[3]), "r"(b[0]), "r"(b[1]));
}
// permuted W lookup: k<20 -> dist weight row 7+k ; 20..26 -> node row k-20 ; else 0
__device__ __forceinline__ float wval(const float* __restrict__ W, int k, int n) {
    if (k < 20) return W[(7 + k) * 64 + n];
    if (k < 27) return W[(k - 20) * 64 + n];
    return 0.0f;
}

// ---- pre-kernel: build B fragment table (single fp16, scale-folded) + shift ----
__global__ void lef_prep(const float* __restrict__ W, const float* __restrict__ gamma_,
                         const float* __restrict__ beta_, const float* __restrict__ rmean,
                         const float* __restrict__ rvar)
{
    const int t = threadIdx.x;                    // 64 threads
    {
        const float s = gamma_[t] * rsqrtf(rvar[t] + 1e-3f);
        g_shift[t] = beta_[t] - rmean[t] * s;
    }
    const int h = t >> 5, lane = t & 31, t4 = lane & 3, gg = lane >> 2;
    uint32_t vals[16];
    #pragma unroll
    for (int nt = 0; nt < 4; ++nt) {
        const int nn = h * 32 + nt * 8 + gg;
        const float s = gamma_[nn] * rsqrtf(rvar[nn] + 1e-3f);
        #pragma unroll
        for (int ks = 0; ks < 2; ++ks) {
            const int k0 = ks * 16 + 2 * t4;
            const float w00 = wval(W, k0,     nn) * s;
            const float w01 = wval(W, k0 + 1, nn) * s;
            const float w10 = wval(W, k0 + 8, nn) * s;
            const float w11 = wval(W, k0 + 9, nn) * s;
            vals[(nt * 2 + ks) * 2 + 0] = pack_h2(w00, w01);
            vals[(nt * 2 + ks) * 2 + 1] = pack_h2(w10, w11);
        }
    }
    uint32_t* dst = &g_Btab[(h * 32 + lane) * 16];
    #pragma unroll
    for (int i = 0; i < 16; ++i) dst[i] = vals[i];
}

__global__ void __launch_bounds__(THREADS, 12) lef_mma8_kernel(
    const float4* __restrict__ feats4,
    const int*    __restrict__ num_points,
    float* __restrict__ out,
    int V)
{
    __shared__ __align__(16) uint8_t Amat[WARPS][ROWS * ASTR];   // fp16, single matrix
    __shared__ float4 cs4s[WARPS * VPW][PP];
    __shared__ float  meanv[WARPS * VPW][3];
    __shared__ int    npvs[WARPS * VPW];
    __shared__ __align__(8) float shfs[64];

    const int tid  = threadIdx.x;
    const int warp = tid >> 5;
    const int lane = tid & 31;
    const int t4 = lane & 3, g = lane >> 2;

    if (tid < 64) shfs[tid] = g_shift[tid];

    // ---- stage features (coalesced LDG.128) ----
    const int v0 = (blockIdx.x * WARPS + warp) * VPW;
    for (int t = lane; t < VPW * PP; t += 32) {
        const int vi = t / PP, p = t - vi * PP;
        const int vv = v0 + vi;
        float4 f = make_float4(0.f, 0.f, 0.f, 0.f);
        if (vv < V) f = feats4[(size_t)v0 * PP + t];
        cs4s[warp * VPW + vi][p] = f;
    }
    if (lane < VPW) {
        const int vv = v0 + lane;
        npvs[warp * VPW + lane] = (vv < V) ? num_points[vv] : 1;
    }
    __syncwarp();

    // ---- per-voxel means (unmasked sum / npts, as reference) ----
    if (lane < 12) {
        const int vi = lane / 3, d = lane - vi * 3;
        const int sv = warp * VPW + vi;
        const float* c = (const float*)&cs4s[sv][0];
        float s = 0.0f;
        #pragma unroll
        for (int p = 0; p < PP; ++p) s += c[p * 4 + d];
        meanv[sv][d] = s / (float)npvs[sv];
    }
    __syncwarp();

    // ---- assemble A rows (single fp16), direct-difference distances ----
    // row r<64: voxel r>>4, point r&15 ; row 64+j: voxel j>>2, point 16+(j&3)
    const uint32_t aB = smem_u32(&Amat[warp][0]);
    #pragma unroll
    for (int r = lane; r < ROWS; r += 32) {
        int vi, p;
        if (r < 64) { vi = r >> 4; p = r & 15; }
        else        { vi = (r - 64) >> 2; p = 16 + ((r - 64) & 3); }
        const int sv = warp * VPW + vi;
        const float4 a  = cs4s[sv][p];
        const int   np  = npvs[sv];
        const float pm  = (p < np) ? 1.0f : 0.0f;
        const float m0 = meanv[sv][0], m1 = meanv[sv][1], m2 = meanv[sv][2];

        uint32_t hi[16];
        #pragma unroll
        for (int jj = 0; jj < 10; ++jj) {
            const int q0 = 2 * jj, q1 = q0 + 1;
            const float4 b0 = cs4s[sv][q0], b1 = cs4s[sv][q1];
            const float dx0 = a.x - b0.x, dy0 = a.y - b0.y, dz0 = a.z - b0.z;
            const float dx1 = a.x - b1.x, dy1 = a.y - b1.y, dz1 = a.z - b1.z;
            float d20 = dx0 * dx0; d20 = fmaf(dy0, dy0, d20); d20 = fmaf(dz0, dz0, d20);
            float d21 = dx1 * dx1; d21 = fmaf(dy1, dy1, d21); d21 = fmaf(dz1, dz1, d21);
            const float e0 = (d20 > 0.0f && q0 < np) ? sqrt_apx(d20) : 0.0f;
            const float e1 = (d21 > 0.0f && q1 < np) ? sqrt_apx(d21) : 0.0f;
            hi[jj] = pack_h2(e0, e1);
        }
        const float n0 = a.x * pm, n1 = a.y * pm, n2 = a.z * pm, n3 = a.w * pm;
        const float n4 = (a.x - m0) * pm, n5 = (a.y - m1) * pm, n6 = (a.z - m2) * pm;
        hi[10] = pack_h2(n0, n1);
        hi[11] = pack_h2(n2, n3);
        hi[12] = pack_h2(n4, n5);
        hi[13] = pack_h2(n6, 0.f);
        hi[14] = hi[15] = 0u;

        uint8_t* rowA = &Amat[warp][r * ASTR];
        const int rot = (lane >> 3) & 3;              // de-conflict STS banks
        #pragma unroll
        for (int jj = 0; jj < 4; ++jj) {
            const int j = (jj + rot) & 3;
            *(uint4*)(rowA + j * 16) = make_uint4(hi[4*j], hi[4*j+1], hi[4*j+2], hi[4*j+3]);
        }
    }
    __syncthreads();   // A tiles + shfs visible

    const int vsel = g >> 2;   // tile-4 voxel owned by acc4[.][0..1]; [2..3] -> vsel+2

    // ---- two 32-column halves ----
    #pragma unroll 1
    for (int h = 0; h < 2; ++h) {
        // B fragments from precomputed table (L1-hot broadcast), single fp16
        uint32_t BH[16];
        {
            const uint4* bt = (const uint4*)&g_Btab[(h * 32 + lane) * 16];
            #pragma unroll
            for (int i = 0; i < 4; ++i) {
                const uint4 q = bt[i];
                BH[4*i] = q.x; BH[4*i+1] = q.y; BH[4*i+2] = q.z; BH[4*i+3] = q.w;
            }
        }
        #define BHF(nt, ks) (&BH[((nt) * 2 + (ks)) * 2])

        // tile 4 first (leftover points p=16..19 of all 4 voxels), hold acc4
        float acc4[4][4];
        {
            uint32_t a4[2][4];
            const uint32_t ro4 = (uint32_t)((64 + (lane & 15)) * ASTR + (lane >> 4) * 16);
            ldmat4(a4[0], aB + ro4);      ldmat4(a4[1], aB + ro4 + 32);
            #pragma unroll
            for (int nt = 0; nt < 4; ++nt)
                acc4[nt][0] = acc4[nt][1] = acc4[nt][2] = acc4[nt][3] = 0.0f;
            #pragma unroll
            for (int ks = 0; ks < 2; ++ks)
                #pragma unroll
                for (int nt = 0; nt < 4; ++nt)
                    mma16816(acc4[nt], a4[ks], BHF(nt, ks));
        }

        // per-voxel tiles + lean shuffle-max epilogue
        #pragma unroll
        for (int vi = 0; vi < VPW; ++vi) {
            uint32_t af[2][4];
            const uint32_t ro = (uint32_t)((vi * 16 + (lane & 15)) * ASTR + (lane >> 4) * 16);
            ldmat4(af[0], aB + ro);      ldmat4(af[1], aB + ro + 32);
            float acc[4][4];
            #pragma unroll
            for (int nt = 0; nt < 4; ++nt)
                acc[nt][0] = acc[nt][1] = acc[nt][2] = acc[nt][3] = 0.0f;
            #pragma unroll
            for (int ks = 0; ks < 2; ++ks)
                #pragma unroll
                for (int nt = 0; nt < 4; ++nt)
                    mma16816(acc[nt], af[ks], BHF(nt, ks));

            // per-lane max over this voxel's rows (p 0..15), merge tile-4 rows
            float pmx[8];
            #pragma unroll
            for (int nt = 0; nt < 4; ++nt) {
                pmx[2*nt]   = fmaxf(acc[nt][0], acc[nt][2]);
                pmx[2*nt+1] = fmaxf(acc[nt][1], acc[nt][3]);
            }
            if (vsel == vi) {
                #pragma unroll
                for (int nt = 0; nt < 4; ++nt) {
                    pmx[2*nt]   = fmaxf(pmx[2*nt],   acc4[nt][0]);
                    pmx[2*nt+1] = fmaxf(pmx[2*nt+1], acc4[nt][1]);
                }
            }
            if (vsel == vi - 2) {
                #pragma unroll
                for (int nt = 0; nt < 4; ++nt) {
                    pmx[2*nt]   = fmaxf(pmx[2*nt],   acc4[nt][2]);
                    pmx[2*nt+1] = fmaxf(pmx[2*nt+1], acc4[nt][3]);
                }
            }

            // lean butterfly: drop half the values each round
            const bool b4 = (lane & 16) != 0;
            float q[4];
            #pragma unroll
            for (int i = 0; i < 4; ++i) {
                const float send = b4 ? pmx[i] : pmx[4 + i];
                const float recv = __shfl_xor_sync(0xffffffffu, send, 16);
                q[i] = fmaxf(b4 ? pmx[4 + i] : pmx[i], recv);
            }
            const bool b3 = (lane & 8) != 0;
            float r2v[2];
            #pragma unroll
            for (int i = 0; i < 2; ++i) {
                const float send = b3 ? q[i] : q[2 + i];
                const float recv = __shfl_xor_sync(0xffffffffu, send, 8);
                r2v[i] = fmaxf(b3 ? q[2 + i] : q[i], recv);
            }
            const float f0 = fmaxf(r2v[0], __shfl_xor_sync(0xffffffffu, r2v[0], 4));
            const float f1 = fmaxf(r2v[1], __shfl_xor_sync(0xffffffffu, r2v[1], 4));

            // lanes with bit2==0 store cols ntp*8 + 2*t4 (+1)
            const int vv = v0 + vi;
            if ((lane & 4) == 0 && vv < V) {
                const int ntp = (((lane >> 4) & 1) << 1) | ((lane >> 3) & 1);
                const int col = h * 32 + ntp * 8 + 2 * t4;
                const float2 sh = *(const float2*)&shfs[col];
                float2 r2;
                r2.x = fmaxf(0.0f, f0 + sh.x);
                r2.y = fmaxf(0.0f, f1 + sh.y);
                *(float2*)&out[(size_t)vv * 64 + col] = r2;
            }
        }
        #undef BHF
    }
}

extern "C" void kernel_launch(void* const* d_in, const int* in_sizes, int n_in,
                              void* d_out, int out_size) {
    const float4* feats4     = (const float4*)d_in[0];
    const int*    num_points = (const int*)   d_in[1];
    const float*  W          = (const float*) d_in[3];
    const float*  gamma_     = (const float*) d_in[4];
    const float*  beta_      = (const float*) d_in[5];
    const float*  rmean      = (const float*) d_in[6];
    const float*  rvar       = (const float*) d_in[7];
    float* out = (float*)d_out;

    const int V = in_sizes[1];
    lef_prep<<<1, 64>>>(W, gamma_, beta_, rmean, rvar);
    const int vox_per_cta = WARPS * VPW;
    const int grid = (V + vox_per_cta - 1) / vox_per_cta;
    lef_mma8_kernel<<<grid, THREADS>>>(feats4, num_points, out, V);
}

// round 13
// speedup vs baseline: 1.6483x; 1.0517x over previous
#include <cuda_runtime.h>
#include <cuda_fp16.h>
#include <stdint.h>

#define PP 20
#define VPW 4          // voxels per warp
#define WARPS 2
#define THREADS 64
#define ROWS 80        // A rows per warp = 5 m16 tiles
#define ASTR 80        // bytes per A row (32 fp16 = 64B data + 16B pad)

// precomputed by lef_prep: B fragments (BN-scale folded, permuted, single fp16)
// layout: [h(2)][lane(32)][16]   (idx = (nt*2+ks)*2+pair)
__device__ uint32_t g_Btab[2 * 32 * 16];
__device__ __align__(16) float g_shift[64];

__device__ __forceinline__ uint32_t smem_u32(const void* p) {
    uint32_t a;
    asm("{ .reg .u64 t; cvta.to.shared.u64 t, %1; cvt.u32.u64 %0, t; }" : "=r"(a) : "l"(p));
    return a;
}
__device__ __forceinline__ float sqrt_apx(float x) {
    float r; asm("sqrt.approx.f32 %0,%1;" : "=f"(r) : "f"(x)); return r;
}
__device__ __forceinline__ uint32_t pack_h2(float x, float y) {
    __half2 t = __floats2half2_rn(x, y);
    return *(uint32_t*)&t;
}
__device__ __forceinline__ uint32_t hmul2u(uint32_t a, uint32_t b) {
    __half2 r = __hmul2(*(__half2*)&a, *(__half2*)&b);
    return *(uint32_t*)&r;
}
__device__ __forceinline__ void ldmat4(uint32_t* r, uint32_t addr) {
    asm volatile("ldmatrix.sync.aligned.m8n8.x4.shared.b16 {%0,%1,%2,%3}, [%4];"
        : "=r"(r[0]), "=r"(r[1]), "=r"(r[2]), "=r"(r[3]) : "r"(addr));
}
__device__ __forceinline__ void mma16816(float* c, const uint32_t* a, const uint32_t* b) {
    asm volatile("mma.sync.aligned.m16n8k16.row.col.f32.f16.f16.f32 "
        "{%0,%1,%2,%3},{%4,%5,%6,%7},{%8,%9},{%0,%1,%2,%3};"
        : "+f"(c[0]), "+f"(c[1]), "+f"(c[2]), "+f"(c[3])
        : "r"(a[0]), "r"(a[1]), "r"(a[2]), "r"(a[3]), "r"(b[0]), "r"(b[1]));
}
// first-k MMA: d = a*b + 0  (no accumulator init MOVs needed)
__device__ __forceinline__ void mma16816_zc(float* d, const uint32_t* a, const uint32_t* b) {
    asm volatile("mma.sync.aligned.m16n8k16.row.col.f32.f16.f16.f32 "
        "{%0,%1,%2,%3},{%4,%5,%6,%7},{%8,%9},{%10,%10,%10,%10};"
        : "=f"(d[0]), "=f"(d[1]), "=f"(d[2]), "=f"(d[3])
        : "r"(a[0]), "r"(a[1]), "r"(a[2]), "r"(a[3]), "r"(b[0]), "r"(b[1]),
          "f"(0.0f));
}
// permuted W lookup: k<20 -> dist weight row 7+k ; 20..26 -> node row k-20 ; else 0
__device__ __forceinline__ float wval(const float* __restrict__ W, int k, int n) {
    if (k < 20) return W[(7 + k) * 64 + n];
    if (k < 27) return W[(k - 20) * 64 + n];
    return 0.0f;
}

// ---- pre-kernel: build B fragment table (single fp16, scale-folded) + shift ----
__global__ void lef_prep(const float* __restrict__ W, const float* __restrict__ gamma_,
                         const float* __restrict__ beta_, const float* __restrict__ rmean,
                         const float* __restrict__ rvar)
{
    const int t = threadIdx.x;                    // 64 threads
    {
        const float s = gamma_[t] * rsqrtf(rvar[t] + 1e-3f);
        g_shift[t] = beta_[t] - rmean[t] * s;
    }
    const int h = t >> 5, lane = t & 31, t4 = lane & 3, gg = lane >> 2;
    uint32_t vals[16];
    #pragma unroll
    for (int nt = 0; nt < 4; ++nt) {
        const int nn = h * 32 + nt * 8 + gg;
        const float s = gamma_[nn] * rsqrtf(rvar[nn] + 1e-3f);
        #pragma unroll
        for (int ks = 0; ks < 2; ++ks) {
            const int k0 = ks * 16 + 2 * t4;
            const float w00 = wval(W, k0,     nn) * s;
            const float w01 = wval(W, k0 + 1, nn) * s;
            const float w10 = wval(W, k0 + 8, nn) * s;
            const float w11 = wval(W, k0 + 9, nn) * s;
            vals[(nt * 2 + ks) * 2 + 0] = pack_h2(w00, w01);
            vals[(nt * 2 + ks) * 2 + 1] = pack_h2(w10, w11);
        }
    }
    uint32_t* dst = &g_Btab[(h * 32 + lane) * 16];
    #pragma unroll
    for (int i = 0; i < 16; ++i) dst[i] = vals[i];
}

__global__ void __launch_bounds__(THREADS, 12) lef_mma9_kernel(
    const float4* __restrict__ feats4,
    const int*    __restrict__ num_points,
    float* __restrict__ out,
    int V)
{
    __shared__ __align__(16) uint8_t Amat[WARPS][ROWS * ASTR];   // fp16, single matrix
    __shared__ float4 cs4s[WARPS * VPW][PP];
    __shared__ float  meanv[WARPS * VPW][3];
    __shared__ int    npvs[WARPS * VPW];
    __shared__ __align__(16) uint32_t qm2s[WARPS * VPW][12];     // q<np half2 masks (10 used)
    __shared__ __align__(8) float shfs[64];

    const int tid  = threadIdx.x;
    const int warp = tid >> 5;
    const int lane = tid & 31;
    const int t4 = lane & 3, g = lane >> 2;

    if (tid < 64) shfs[tid] = g_shift[tid];

    // ---- stage features (coalesced LDG.128) ----
    const int v0 = (blockIdx.x * WARPS + warp) * VPW;
    for (int t = lane; t < VPW * PP; t += 32) {
        const int vi = t / PP, p = t - vi * PP;
        const int vv = v0 + vi;
        float4 f = make_float4(0.f, 0.f, 0.f, 0.f);
        if (vv < V) f = feats4[(size_t)v0 * PP + t];
        cs4s[warp * VPW + vi][p] = f;
    }
    if (lane < VPW) {
        const int vv = v0 + lane;
        npvs[warp * VPW + lane] = (vv < V) ? num_points[vv] : 1;
    }
    __syncwarp();

    // ---- per-voxel means + q-mask tables ----
    if (lane < 12) {
        const int vi = lane / 3, d = lane - vi * 3;
        const int sv = warp * VPW + vi;
        const float* c = (const float*)&cs4s[sv][0];
        float s = 0.0f;
        #pragma unroll
        for (int p = 0; p < PP; ++p) s += c[p * 4 + d];
        meanv[sv][d] = s / (float)npvs[sv];
    }
    for (int t = lane; t < VPW * 12; t += 32) {
        const int vi = t / 12, jj = t - vi * 12;
        const int sv = warp * VPW + vi;
        const int np = npvs[sv];
        const float q0m = (2 * jj     < np) ? 1.0f : 0.0f;
        const float q1m = (2 * jj + 1 < np) ? 1.0f : 0.0f;
        qm2s[sv][jj] = (jj < 10) ? pack_h2(q0m, q1m) : 0u;
    }
    __syncwarp();

    // ---- assemble A rows (single fp16), unpredicated distances ----
    // row r<64: voxel r>>4, point r&15 ; row 64+j: voxel j>>2, point 16+(j&3)
    const uint32_t aB = smem_u32(&Amat[warp][0]);
    #pragma unroll
    for (int r = lane; r < ROWS; r += 32) {
        int vi, p;
        if (r < 64) { vi = r >> 4; p = r & 15; }
        else        { vi = (r - 64) >> 2; p = 16 + ((r - 64) & 3); }
        const int sv = warp * VPW + vi;
        const float4 a  = cs4s[sv][p];
        const int   np  = npvs[sv];
        const float pm  = (p < np) ? 1.0f : 0.0f;
        const float m0 = meanv[sv][0], m1 = meanv[sv][1], m2 = meanv[sv][2];

        // q-mask multipliers for this voxel (3 vector LDS)
        const uint4 qa = *(const uint4*)&qm2s[sv][0];
        const uint4 qb = *(const uint4*)&qm2s[sv][4];
        const uint2 qc = *(const uint2*)&qm2s[sv][8];
        const uint32_t qm[10] = { qa.x, qa.y, qa.z, qa.w, qb.x, qb.y, qb.z, qb.w, qc.x, qc.y };

        uint32_t hi[16];
        #pragma unroll
        for (int jj = 0; jj < 10; ++jj) {
            const int q0 = 2 * jj, q1 = q0 + 1;
            const float4 b0 = cs4s[sv][q0], b1 = cs4s[sv][q1];
            const float dx0 = a.x - b0.x, dy0 = a.y - b0.y, dz0 = a.z - b0.z;
            const float dx1 = a.x - b1.x, dy1 = a.y - b1.y, dz1 = a.z - b1.z;
            float d20 = dx0 * dx0; d20 = fmaf(dy0, dy0, d20); d20 = fmaf(dz0, dz0, d20);
            float d21 = dx1 * dx1; d21 = fmaf(dy1, dy1, d21); d21 = fmaf(dz1, dz1, d21);
            // d2 >= 0 always; p==q gives exactly 0 -> sqrt.approx(0) = 0. No predicate.
            hi[jj] = hmul2u(pack_h2(sqrt_apx(d20), sqrt_apx(d21)), qm[jj]);
        }
        const float n0 = a.x * pm, n1 = a.y * pm, n2 = a.z * pm, n3 = a.w * pm;
        const float n4 = (a.x - m0) * pm, n5 = (a.y - m1) * pm, n6 = (a.z - m2) * pm;
        hi[10] = pack_h2(n0, n1);
        hi[11] = pack_h2(n2, n3);
        hi[12] = pack_h2(n4, n5);
        hi[13] = pack_h2(n6, 0.f);
        hi[14] = hi[15] = 0u;

        uint8_t* rowA = &Amat[warp][r * ASTR];
        const int rot = (lane >> 3) & 3;              // de-conflict STS banks
        #pragma unroll
        for (int jj = 0; jj < 4; ++jj) {
            const int j = (jj + rot) & 3;
            *(uint4*)(rowA + j * 16) = make_uint4(hi[4*j], hi[4*j+1], hi[4*j+2], hi[4*j+3]);
        }
    }
    __syncthreads();   // A tiles + shfs visible

    const int vsel = g >> 2;   // tile-4 voxel owned by acc4[.][0..1]; [2..3] -> vsel+2

    // ---- two 32-column halves ----
    #pragma unroll 1
    for (int h = 0; h < 2; ++h) {
        // B fragments from precomputed table (L1-hot broadcast), single fp16
        uint32_t BH[16];
        {
            const uint4* bt = (const uint4*)&g_Btab[(h * 32 + lane) * 16];
            #pragma unroll
            for (int i = 0; i < 4; ++i) {
                const uint4 q = bt[i];
                BH[4*i] = q.x; BH[4*i+1] = q.y; BH[4*i+2] = q.z; BH[4*i+3] = q.w;
            }
        }
        #define BHF(nt, ks) (&BH[((nt) * 2 + (ks)) * 2])

        // tile 4 first (leftover points p=16..19 of all 4 voxels), hold acc4
        float acc4[4][4];
        {
            uint32_t a4[2][4];
            const uint32_t ro4 = (uint32_t)((64 + (lane & 15)) * ASTR + (lane >> 4) * 16);
            ldmat4(a4[0], aB + ro4);      ldmat4(a4[1], aB + ro4 + 32);
            #pragma unroll
            for (int nt = 0; nt < 4; ++nt) {
                mma16816_zc(acc4[nt], a4[0], BHF(nt, 0));   // ks=0, zero C
                mma16816  (acc4[nt], a4[1], BHF(nt, 1));    // ks=1, accumulate
            }
        }

        // per-voxel tiles + lean shuffle-max epilogue
        #pragma unroll
        for (int vi = 0; vi < VPW; ++vi) {
            uint32_t af[2][4];
            const uint32_t ro = (uint32_t)((vi * 16 + (lane & 15)) * ASTR + (lane >> 4) * 16);
            ldmat4(af[0], aB + ro);      ldmat4(af[1], aB + ro + 32);
            float acc[4][4];
            #pragma unroll
            for (int nt = 0; nt < 4; ++nt) {
                mma16816_zc(acc[nt], af[0], BHF(nt, 0));
                mma16816  (acc[nt], af[1], BHF(nt, 1));
            }

            // per-lane max over this voxel's rows (p 0..15), merge tile-4 rows
            float pmx[8];
            #pragma unroll
            for (int nt = 0; nt < 4; ++nt) {
                pmx[2*nt]   = fmaxf(acc[nt][0], acc[nt][2]);
                pmx[2*nt+1] = fmaxf(acc[nt][1], acc[nt][3]);
            }
            if (vsel == vi) {
                #pragma unroll
                for (int nt = 0; nt < 4; ++nt) {
                    pmx[2*nt]   = fmaxf(pmx[2*nt],   acc4[nt][0]);
                    pmx[2*nt+1] = fmaxf(pmx[2*nt+1], acc4[nt][1]);
                }
            }
            if (vsel == vi - 2) {
                #pragma unroll
                for (int nt = 0; nt < 4; ++nt) {
                    pmx[2*nt]   = fmaxf(pmx[2*nt],   acc4[nt][2]);
                    pmx[2*nt+1] = fmaxf(pmx[2*nt+1], acc4[nt][3]);
                }
            }

            // lean butterfly: drop half the values each round
            const bool b4 = (lane & 16) != 0;
            float q[4];
            #pragma unroll
            for (int i = 0; i < 4; ++i) {
                const float send = b4 ? pmx[i] : pmx[4 + i];
                const float recv = __shfl_xor_sync(0xffffffffu, send, 16);
                q[i] = fmaxf(b4 ? pmx[4 + i] : pmx[i], recv);
            }
            const bool b3 = (lane & 8) != 0;
            float r2v[2];
            #pragma unroll
            for (int i = 0; i < 2; ++i) {
                const float send = b3 ? q[i] : q[2 + i];
                const float recv = __shfl_xor_sync(0xffffffffu, send, 8);
                r2v[i] = fmaxf(b3 ? q[2 + i] : q[i], recv);
            }
            const float f0 = fmaxf(r2v[0], __shfl_xor_sync(0xffffffffu, r2v[0], 4));
            const float f1 = fmaxf(r2v[1], __shfl_xor_sync(0xffffffffu, r2v[1], 4));

            // lanes with bit2==0 store cols ntp*8 + 2*t4 (+1)
            const int vv = v0 + vi;
            if ((lane & 4) == 0 && vv < V) {
                const int ntp = (((lane >> 4) & 1) << 1) | ((lane >> 3) & 1);
                const int col = h * 32 + ntp * 8 + 2 * t4;
                const float2 sh = *(const float2*)&shfs[col];
                float2 r2;
                r2.x = fmaxf(0.0f, f0 + sh.x);
                r2.y = fmaxf(0.0f, f1 + sh.y);
                *(float2*)&out[(size_t)vv * 64 + col] = r2;
            }
        }
        #undef BHF
    }
}

extern "C" void kernel_launch(void* const* d_in, const int* in_sizes, int n_in,
                              void* d_out, int out_size) {
    const float4* feats4     = (const float4*)d_in[0];
    const int*    num_points = (const int*)   d_in[1];
    const float*  W          = (const float*) d_in[3];
    const float*  gamma_     = (const float*) d_in[4];
    const float*  beta_      = (const float*) d_in[5];
    const float*  rmean      = (const float*) d_in[6];
    const float*  rvar       = (const float*) d_in[7];
    float* out = (float*)d_out;

    const int V = in_sizes[1];
    lef_prep<<<1, 64>>>(W, gamma_, beta_, rmean, rvar);
    const int vox_per_cta = WARPS * VPW;
    const int grid = (V + vox_per_cta - 1) / vox_per_cta;
    lef_mma9_kernel<<<grid, THREADS>>>(feats4, num_points, out, V);
}

// round 14
// speedup vs baseline: 1.6652x; 1.0102x over previous
#include <cuda_runtime.h>
#include <cuda_fp16.h>
#include <stdint.h>

#define PP 20
#define VPW 4          // voxels per warp
#define WARPS 2
#define THREADS 64
#define ROWS 80        // A rows per warp = 5 m16 tiles
#define ASTR 80        // bytes per A row (32 fp16 = 64B data + 16B pad)

// precomputed by lef_prep: B fragments (BN-scale folded, permuted, single fp16)
// channel 27 carries the BN shift (x[27] == 1.0 in every row)
// layout: [h(2)][lane(32)][16]   (idx = (nt*2+ks)*2+pair)
__device__ uint32_t g_Btab[2 * 32 * 16];

__device__ __forceinline__ uint32_t smem_u32(const void* p) {
    uint32_t a;
    asm("{ .reg .u64 t; cvta.to.shared.u64 t, %1; cvt.u32.u64 %0, t; }" : "=r"(a) : "l"(p));
    return a;
}
__device__ __forceinline__ float sqrt_apx(float x) {
    float r; asm("sqrt.approx.f32 %0,%1;" : "=f"(r) : "f"(x)); return r;
}
__device__ __forceinline__ uint32_t pack_h2(float x, float y) {
    __half2 t = __floats2half2_rn(x, y);
    return *(uint32_t*)&t;
}
__device__ __forceinline__ uint32_t hmul2u(uint32_t a, uint32_t b) {
    __half2 r = __hmul2(*(__half2*)&a, *(__half2*)&b);
    return *(uint32_t*)&r;
}
__device__ __forceinline__ void ldmat4(uint32_t* r, uint32_t addr) {
    asm volatile("ldmatrix.sync.aligned.m8n8.x4.shared.b16 {%0,%1,%2,%3}, [%4];"
        : "=r"(r[0]), "=r"(r[1]), "=r"(r[2]), "=r"(r[3]) : "r"(addr));
}
__device__ __forceinline__ void mma16816(float* c, const uint32_t* a, const uint32_t* b) {
    asm volatile("mma.sync.aligned.m16n8k16.row.col.f32.f16.f16.f32 "
        "{%0,%1,%2,%3},{%4,%5,%6,%7},{%8,%9},{%0,%1,%2,%3};"
        : "+f"(c[0]), "+f"(c[1]), "+f"(c[2]), "+f"(c[3])
        : "r"(a[0]), "r"(a[1]), "r"(a[2]), "r"(a[3]), "r"(b[0]), "r"(b[1]));
}
// first-k MMA: d = a*b + 0  (no accumulator init MOVs needed)
__device__ __forceinline__ void mma16816_zc(float* d, const uint32_t* a, const uint32_t* b) {
    asm volatile("mma.sync.aligned.m16n8k16.row.col.f32.f16.f16.f32 "
        "{%0,%1,%2,%3},{%4,%5,%6,%7},{%8,%9},{%10,%10,%10,%10};"
        : "=f"(d[0]), "=f"(d[1]), "=f"(d[2]), "=f"(d[3])
        : "r"(a[0]), "r"(a[1]), "r"(a[2]), "r"(a[3]), "r"(b[0]), "r"(b[1]),
          "f"(0.0f));
}
// permuted W lookup: k<20 -> dist weight row 7+k ; 20..26 -> node row k-20 ; else 0
__device__ __forceinline__ float wval(const float* __restrict__ W, int k, int n) {
    if (k < 20) return W[(7 + k) * 64 + n];
    if (k < 27) return W[(k - 20) * 64 + n];
    return 0.0f;
}

// ---- pre-kernel: build B fragment table (single fp16, scale-folded, shift@27) ----
__global__ void lef_prep(const float* __restrict__ W, const float* __restrict__ gamma_,
                         const float* __restrict__ beta_, const float* __restrict__ rmean,
                         const float* __restrict__ rvar)
{
    const int t = threadIdx.x;                    // 64 threads
    const int h = t >> 5, lane = t & 31, t4 = lane & 3, gg = lane >> 2;
    uint32_t vals[16];
    #pragma unroll
    for (int nt = 0; nt < 4; ++nt) {
        const int nn = h * 32 + nt * 8 + gg;
        const float s = gamma_[nn] * rsqrtf(rvar[nn] + 1e-3f);
        const float shift = beta_[nn] - rmean[nn] * s;
        #pragma unroll
        for (int ks = 0; ks < 2; ++ks) {
            const int k0 = ks * 16 + 2 * t4;
            const int kk[4] = { k0, k0 + 1, k0 + 8, k0 + 9 };
            float wv[4];
            #pragma unroll
            for (int i = 0; i < 4; ++i) {
                const int k = kk[i];
                wv[i] = (k == 27) ? shift : wval(W, k, nn) * s;
            }
            vals[(nt * 2 + ks) * 2 + 0] = pack_h2(wv[0], wv[1]);
            vals[(nt * 2 + ks) * 2 + 1] = pack_h2(wv[2], wv[3]);
        }
    }
    uint32_t* dst = &g_Btab[(h * 32 + lane) * 16];
    #pragma unroll
    for (int i = 0; i < 16; ++i) dst[i] = vals[i];
}

__global__ void __launch_bounds__(THREADS, 13) lef_mma10_kernel(
    const float4* __restrict__ feats4,
    const int*    __restrict__ num_points,
    float* __restrict__ out,
    int V)
{
    __shared__ __align__(16) uint8_t Amat[WARPS][ROWS * ASTR];   // fp16, single matrix
    __shared__ float4 cs4s[WARPS * VPW][PP];
    __shared__ float  meanv[WARPS * VPW][3];
    __shared__ int    npvs[WARPS * VPW];
    __shared__ __align__(16) uint32_t qm2s[WARPS * VPW][12];     // q<np half2 masks (10 used)

    const int tid  = threadIdx.x;
    const int warp = tid >> 5;
    const int lane = tid & 31;
    const int t4 = lane & 3, g = lane >> 2;

    // ---- stage features (coalesced LDG.128) ----
    const int v0 = (blockIdx.x * WARPS + warp) * VPW;
    for (int t = lane; t < VPW * PP; t += 32) {
        const int vi = t / PP, p = t - vi * PP;
        const int vv = v0 + vi;
        float4 f = make_float4(0.f, 0.f, 0.f, 0.f);
        if (vv < V) f = feats4[(size_t)v0 * PP + t];
        cs4s[warp * VPW + vi][p] = f;
    }
    if (lane < VPW) {
        const int vv = v0 + lane;
        npvs[warp * VPW + lane] = (vv < V) ? num_points[vv] : 1;
    }
    __syncwarp();

    // ---- per-voxel means + q-mask tables ----
    if (lane < 12) {
        const int vi = lane / 3, d = lane - vi * 3;
        const int sv = warp * VPW + vi;
        const float* c = (const float*)&cs4s[sv][0];
        float s = 0.0f;
        #pragma unroll
        for (int p = 0; p < PP; ++p) s += c[p * 4 + d];
        meanv[sv][d] = s / (float)npvs[sv];
    }
    for (int t = lane; t < VPW * 12; t += 32) {
        const int vi = t / 12, jj = t - vi * 12;
        const int sv = warp * VPW + vi;
        const int np = npvs[sv];
        const float q0m = (2 * jj     < np) ? 1.0f : 0.0f;
        const float q1m = (2 * jj + 1 < np) ? 1.0f : 0.0f;
        qm2s[sv][jj] = (jj < 10) ? pack_h2(q0m, q1m) : 0u;
    }
    __syncwarp();

    // ---- assemble A rows (single fp16), unpredicated distances ----
    // row r<64: voxel r>>4, point r&15 ; row 64+j: voxel j>>2, point 16+(j&3)
    const uint32_t aB = smem_u32(&Amat[warp][0]);
    #pragma unroll
    for (int r = lane; r < ROWS; r += 32) {
        int vi, p;
        if (r < 64) { vi = r >> 4; p = r & 15; }
        else        { vi = (r - 64) >> 2; p = 16 + ((r - 64) & 3); }
        const int sv = warp * VPW + vi;
        const float4 a  = cs4s[sv][p];
        const int   np  = npvs[sv];
        const float pm  = (p < np) ? 1.0f : 0.0f;
        const float m0 = meanv[sv][0], m1 = meanv[sv][1], m2 = meanv[sv][2];

        // q-mask multipliers for this voxel (3 vector LDS)
        const uint4 qa = *(const uint4*)&qm2s[sv][0];
        const uint4 qb = *(const uint4*)&qm2s[sv][4];
        const uint2 qc = *(const uint2*)&qm2s[sv][8];
        const uint32_t qm[10] = { qa.x, qa.y, qa.z, qa.w, qb.x, qb.y, qb.z, qb.w, qc.x, qc.y };

        uint32_t hi[16];
        #pragma unroll
        for (int jj = 0; jj < 10; ++jj) {
            const int q0 = 2 * jj, q1 = q0 + 1;
            const float4 b0 = cs4s[sv][q0], b1 = cs4s[sv][q1];
            const float dx0 = a.x - b0.x, dy0 = a.y - b0.y, dz0 = a.z - b0.z;
            const float dx1 = a.x - b1.x, dy1 = a.y - b1.y, dz1 = a.z - b1.z;
            float d20 = dx0 * dx0; d20 = fmaf(dy0, dy0, d20); d20 = fmaf(dz0, dz0, d20);
            float d21 = dx1 * dx1; d21 = fmaf(dy1, dy1, d21); d21 = fmaf(dz1, dz1, d21);
            // d2 >= 0 always; p==q gives exactly 0 -> sqrt.approx(0) = 0. No predicate.
            hi[jj] = hmul2u(pack_h2(sqrt_apx(d20), sqrt_apx(d21)), qm[jj]);
        }
        const float n0 = a.x * pm, n1 = a.y * pm, n2 = a.z * pm, n3 = a.w * pm;
        const float n4 = (a.x - m0) * pm, n5 = (a.y - m1) * pm, n6 = (a.z - m2) * pm;
        hi[10] = pack_h2(n0, n1);
        hi[11] = pack_h2(n2, n3);
        hi[12] = pack_h2(n4, n5);
        hi[13] = pack_h2(n6, 1.0f);     // k=27 constant 1 -> B carries BN shift
        hi[14] = hi[15] = 0u;

        uint8_t* rowA = &Amat[warp][r * ASTR];
        const int rot = (lane >> 3) & 3;              // de-conflict STS banks
        #pragma unroll
        for (int jj = 0; jj < 4; ++jj) {
            const int j = (jj + rot) & 3;
            *(uint4*)(rowA + j * 16) = make_uint4(hi[4*j], hi[4*j+1], hi[4*j+2], hi[4*j+3]);
        }
    }
    __syncthreads();   // A tiles visible

    const int vsel = g >> 2;   // tile-4 voxel owned by acc4[.][0..1]; [2..3] -> vsel+2

    // ---- two 32-column halves ----
    #pragma unroll 1
    for (int h = 0; h < 2; ++h) {
        // B fragments from precomputed table (L1-hot broadcast), single fp16
        uint32_t BH[16];
        {
            const uint4* bt = (const uint4*)&g_Btab[(h * 32 + lane) * 16];
            #pragma unroll
            for (int i = 0; i < 4; ++i) {
                const uint4 q = bt[i];
                BH[4*i] = q.x; BH[4*i+1] = q.y; BH[4*i+2] = q.z; BH[4*i+3] = q.w;
            }
        }
        #define BHF(nt, ks) (&BH[((nt) * 2 + (ks)) * 2])

        // tile 4 first (leftover points p=16..19 of all 4 voxels), hold acc4
        float acc4[4][4];
        {
            uint32_t a4[2][4];
            const uint32_t ro4 = (uint32_t)((64 + (lane & 15)) * ASTR + (lane >> 4) * 16);
            ldmat4(a4[0], aB + ro4);      ldmat4(a4[1], aB + ro4 + 32);
            #pragma unroll
            for (int nt = 0; nt < 4; ++nt) {
                mma16816_zc(acc4[nt], a4[0], BHF(nt, 0));   // ks=0, zero C
                mma16816  (acc4[nt], a4[1], BHF(nt, 1));    // ks=1, accumulate
            }
        }

        // per-voxel tiles + lean shuffle-max epilogue
        #pragma unroll
        for (int vi = 0; vi < VPW; ++vi) {
            uint32_t af[2][4];
            const uint32_t ro = (uint32_t)((vi * 16 + (lane & 15)) * ASTR + (lane >> 4) * 16);
            ldmat4(af[0], aB + ro);      ldmat4(af[1], aB + ro + 32);
            float acc[4][4];
            #pragma unroll
            for (int nt = 0; nt < 4; ++nt) {
                mma16816_zc(acc[nt], af[0], BHF(nt, 0));
                mma16816  (acc[nt], af[1], BHF(nt, 1));
            }

            // per-lane max over this voxel's rows (p 0..15), merge tile-4 rows
            float pmx[8];
            #pragma unroll
            for (int nt = 0; nt < 4; ++nt) {
                pmx[2*nt]   = fmaxf(acc[nt][0], acc[nt][2]);
                pmx[2*nt+1] = fmaxf(acc[nt][1], acc[nt][3]);
            }
            if (vsel == vi) {
                #pragma unroll
                for (int nt = 0; nt < 4; ++nt) {
                    pmx[2*nt]   = fmaxf(pmx[2*nt],   acc4[nt][0]);
                    pmx[2*nt+1] = fmaxf(pmx[2*nt+1], acc4[nt][1]);
                }
            }
            if (vsel == vi - 2) {
                #pragma unroll
                for (int nt = 0; nt < 4; ++nt) {
                    pmx[2*nt]   = fmaxf(pmx[2*nt],   acc4[nt][2]);
                    pmx[2*nt+1] = fmaxf(pmx[2*nt+1], acc4[nt][3]);
                }
            }

            // lean butterfly: drop half the values each round
            const bool b4 = (lane & 16) != 0;
            float q[4];
            #pragma unroll
            for (int i = 0; i < 4; ++i) {
                const float send = b4 ? pmx[i] : pmx[4 + i];
                const float recv = __shfl_xor_sync(0xffffffffu, send, 16);
                q[i] = fmaxf(b4 ? pmx[4 + i] : pmx[i], recv);
            }
            const bool b3 = (lane & 8) != 0;
            float r2v[2];
            #pragma unroll
            for (int i = 0; i < 2; ++i) {
                const float send = b3 ? q[i] : q[2 + i];
                const float recv = __shfl_xor_sync(0xffffffffu, send, 8);
                r2v[i] = fmaxf(b3 ? q[2 + i] : q[i], recv);
            }
            const float f0 = fmaxf(r2v[0], __shfl_xor_sync(0xffffffffu, r2v[0], 4));
            const float f1 = fmaxf(r2v[1], __shfl_xor_sync(0xffffffffu, r2v[1], 4));

            // lanes with bit2==0 store cols ntp*8 + 2*t4 (+1); shift already in dot
            const int vv = v0 + vi;
            if ((lane & 4) == 0 && vv < V) {
                const int ntp = (((lane >> 4) & 1) << 1) | ((lane >> 3) & 1);
                const int col = h * 32 + ntp * 8 + 2 * t4;
                float2 r2;
                r2.x = fmaxf(0.0f, f0);
                r2.y = fmaxf(0.0f, f1);
                *(float2*)&out[(size_t)vv * 64 + col] = r2;
            }
        }
        #undef BHF
    }
}

extern "C" void kernel_launch(void* const* d_in, const int* in_sizes, int n_in,
                              void* d_out, int out_size) {
    const float4* feats4     = (const float4*)d_in[0];
    const int*    num_points = (const int*)   d_in[1];
    const float*  W          = (const float*) d_in[3];
    const float*  gamma_     = (const float*) d_in[4];
    const float*  beta_      = (const float*) d_in[5];
    const float*  rmean      = (const float*) d_in[6];
    const float*  rvar       = (const float*) d_in[7];
    float* out = (float*)d_out;

    const int V = in_sizes[1];
    lef_prep<<<1, 64>>>(W, gamma_, beta_, rmean, rvar);
    const int vox_per_cta = WARPS * VPW;
    const int grid = (V + vox_per_cta - 1) / vox_per_cta;
    lef_mma10_kernel<<<grid, THREADS>>>(feats4, num_points, out, V);
}

// round 15
// speedup vs baseline: 1.8072x; 1.0853x over previous
#include <cuda_runtime.h>
#include <cuda_fp16.h>
#include <stdint.h>

#define PP 20
#define VPW 4          // voxels per warp
#define WARPS 2
#define THREADS 64
#define ROWS 80        // A rows per warp = 5 m16 tiles
#define ASTR 64        // bytes per A row (32 fp16, XOR-swizzled chunks, no pad)

// precomputed by lef_prep: B fragments (BN-scale folded, permuted, single fp16)
// channel 27 carries the BN shift (x[27] == 1.0 in every row)
// layout: [h(2)][lane(32)][16]   (idx = (nt*2+ks)*2+pair)
__device__ uint32_t g_Btab[2 * 32 * 16];

__device__ __forceinline__ uint32_t smem_u32(const void* p) {
    uint32_t a;
    asm("{ .reg .u64 t; cvta.to.shared.u64 t, %1; cvt.u32.u64 %0, t; }" : "=r"(a) : "l"(p));
    return a;
}
__device__ __forceinline__ float sqrt_apx(float x) {
    float r; asm("sqrt.approx.f32 %0,%1;" : "=f"(r) : "f"(x)); return r;
}
__device__ __forceinline__ uint32_t pack_h2(float x, float y) {
    __half2 t = __floats2half2_rn(x, y);
    return *(uint32_t*)&t;
}
__device__ __forceinline__ uint32_t hmul2u(uint32_t a, uint32_t b) {
    __half2 r = __hmul2(*(__half2*)&a, *(__half2*)&b);
    return *(uint32_t*)&r;
}
__device__ __forceinline__ void ldmat4(uint32_t* r, uint32_t addr) {
    asm volatile("ldmatrix.sync.aligned.m8n8.x4.shared.b16 {%0,%1,%2,%3}, [%4];"
        : "=r"(r[0]), "=r"(r[1]), "=r"(r[2]), "=r"(r[3]) : "r"(addr));
}
__device__ __forceinline__ void mma16816(float* c, const uint32_t* a, const uint32_t* b) {
    asm volatile("mma.sync.aligned.m16n8k16.row.col.f32.f16.f16.f32 "
        "{%0,%1,%2,%3},{%4,%5,%6,%7},{%8,%9},{%0,%1,%2,%3};"
        : "+f"(c[0]), "+f"(c[1]), "+f"(c[2]), "+f"(c[3])
        : "r"(a[0]), "r"(a[1]), "r"(a[2]), "r"(a[3]), "r"(b[0]), "r"(b[1]));
}
// first-k MMA: d = a*b + 0  (no accumulator init MOVs needed)
__device__ __forceinline__ void mma16816_zc(float* d, const uint32_t* a, const uint32_t* b) {
    asm volatile("mma.sync.aligned.m16n8k16.row.col.f32.f16.f16.f32 "
        "{%0,%1,%2,%3},{%4,%5,%6,%7},{%8,%9},{%10,%10,%10,%10};"
        : "=f"(d[0]), "=f"(d[1]), "=f"(d[2]), "=f"(d[3])
        : "r"(a[0]), "r"(a[1]), "r"(a[2]), "r"(a[3]), "r"(b[0]), "r"(b[1]),
          "f"(0.0f));
}
// permuted W lookup: k<20 -> dist weight row 7+k ; 20..26 -> node row k-20 ; else 0
__device__ __forceinline__ float wval(const float* __restrict__ W, int k, int n) {
    if (k < 20) return W[(7 + k) * 64 + n];
    if (k < 27) return W[(k - 20) * 64 + n];
    return 0.0f;
}

// ---- pre-kernel: build B fragment table (single fp16, scale-folded, shift@27) ----
__global__ void lef_prep(const float* __restrict__ W, const float* __restrict__ gamma_,
                         const float* __restrict__ beta_, const float* __restrict__ rmean,
                         const float* __restrict__ rvar)
{
    const int t = threadIdx.x;                    // 64 threads
    const int h = t >> 5, lane = t & 31, t4 = lane & 3, gg = lane >> 2;
    uint32_t vals[16];
    #pragma unroll
    for (int nt = 0; nt < 4; ++nt) {
        const int nn = h * 32 + nt * 8 + gg;
        const float s = gamma_[nn] * rsqrtf(rvar[nn] + 1e-3f);
        const float shift = beta_[nn] - rmean[nn] * s;
        #pragma unroll
        for (int ks = 0; ks < 2; ++ks) {
            const int k0 = ks * 16 + 2 * t4;
            const int kk[4] = { k0, k0 + 1, k0 + 8, k0 + 9 };
            float wv[4];
            #pragma unroll
            for (int i = 0; i < 4; ++i) {
                const int k = kk[i];
                wv[i] = (k == 27) ? shift : wval(W, k, nn) * s;
            }
            vals[(nt * 2 + ks) * 2 + 0] = pack_h2(wv[0], wv[1]);
            vals[(nt * 2 + ks) * 2 + 1] = pack_h2(wv[2], wv[3]);
        }
    }
    uint32_t* dst = &g_Btab[(h * 32 + lane) * 16];
    #pragma unroll
    for (int i = 0; i < 16; ++i) dst[i] = vals[i];
}

__global__ void __launch_bounds__(THREADS, 15) lef_mma11_kernel(
    const float4* __restrict__ feats4,
    const int*    __restrict__ num_points,
    float* __restrict__ out,
    int V)
{
    __shared__ __align__(16) uint8_t Amat[WARPS][ROWS * ASTR];   // fp16, swizzled chunks
    __shared__ float4 cs4s[WARPS * VPW][PP];
    __shared__ float  meanv[WARPS * VPW][3];
    __shared__ int    npvs[WARPS * VPW];
    __shared__ __align__(16) uint32_t qm2s[WARPS * VPW][12];     // q<np half2 masks (10 used)

    const int tid  = threadIdx.x;
    const int warp = tid >> 5;
    const int lane = tid & 31;
    const int t4 = lane & 3, g = lane >> 2;

    // ---- stage features (coalesced LDG.128) ----
    const int v0 = (blockIdx.x * WARPS + warp) * VPW;
    for (int t = lane; t < VPW * PP; t += 32) {
        const int vi = t / PP, p = t - vi * PP;
        const int vv = v0 + vi;
        float4 f = make_float4(0.f, 0.f, 0.f, 0.f);
        if (vv < V) f = feats4[(size_t)v0 * PP + t];
        cs4s[warp * VPW + vi][p] = f;
    }
    if (lane < VPW) {
        const int vv = v0 + lane;
        npvs[warp * VPW + lane] = (vv < V) ? num_points[vv] : 1;
    }
    __syncwarp();

    // ---- per-voxel means + q-mask tables ----
    if (lane < 12) {
        const int vi = lane / 3, d = lane - vi * 3;
        const int sv = warp * VPW + vi;
        const float* c = (const float*)&cs4s[sv][0];
        float s = 0.0f;
        #pragma unroll
        for (int p = 0; p < PP; ++p) s += c[p * 4 + d];
        meanv[sv][d] = s / (float)npvs[sv];
    }
    for (int t = lane; t < VPW * 12; t += 32) {
        const int vi = t / 12, jj = t - vi * 12;
        const int sv = warp * VPW + vi;
        const int np = npvs[sv];
        const float q0m = (2 * jj     < np) ? 1.0f : 0.0f;
        const float q1m = (2 * jj + 1 < np) ? 1.0f : 0.0f;
        qm2s[sv][jj] = (jj < 10) ? pack_h2(q0m, q1m) : 0u;
    }
    __syncwarp();

    // ---- assemble A rows (single fp16), unpredicated distances ----
    // row r<64: voxel r>>4, point r&15 ; row 64+j: voxel j>>2, point 16+(j&3)
    // chunk j of row r stored at r*64 + ((j ^ ((r>>1)&3)) << 4)  -- conflict-free
    const uint32_t aB = smem_u32(&Amat[warp][0]);
    #pragma unroll
    for (int r = lane; r < ROWS; r += 32) {
        int vi, p;
        if (r < 64) { vi = r >> 4; p = r & 15; }
        else        { vi = (r - 64) >> 2; p = 16 + ((r - 64) & 3); }
        const int sv = warp * VPW + vi;
        const float4 a  = cs4s[sv][p];
        const int   np  = npvs[sv];
        const float pm  = (p < np) ? 1.0f : 0.0f;
        const float m0 = meanv[sv][0], m1 = meanv[sv][1], m2 = meanv[sv][2];

        // q-mask multipliers for this voxel (3 vector LDS)
        const uint4 qa = *(const uint4*)&qm2s[sv][0];
        const uint4 qb = *(const uint4*)&qm2s[sv][4];
        const uint2 qc = *(const uint2*)&qm2s[sv][8];
        const uint32_t qm[10] = { qa.x, qa.y, qa.z, qa.w, qb.x, qb.y, qb.z, qb.w, qc.x, qc.y };

        uint32_t hi[16];
        #pragma unroll
        for (int jj = 0; jj < 10; ++jj) {
            const int q0 = 2 * jj, q1 = q0 + 1;
            const float4 b0 = cs4s[sv][q0], b1 = cs4s[sv][q1];
            const float dx0 = a.x - b0.x, dy0 = a.y - b0.y, dz0 = a.z - b0.z;
            const float dx1 = a.x - b1.x, dy1 = a.y - b1.y, dz1 = a.z - b1.z;
            float d20 = dx0 * dx0; d20 = fmaf(dy0, dy0, d20); d20 = fmaf(dz0, dz0, d20);
            float d21 = dx1 * dx1; d21 = fmaf(dy1, dy1, d21); d21 = fmaf(dz1, dz1, d21);
            // d2 >= 0 always; p==q gives exactly 0 -> sqrt.approx(0) = 0. No predicate.
            hi[jj] = hmul2u(pack_h2(sqrt_apx(d20), sqrt_apx(d21)), qm[jj]);
        }
        const float n0 = a.x * pm, n1 = a.y * pm, n2 = a.z * pm, n3 = a.w * pm;
        const float n4 = (a.x - m0) * pm, n5 = (a.y - m1) * pm, n6 = (a.z - m2) * pm;
        hi[10] = pack_h2(n0, n1);
        hi[11] = pack_h2(n2, n3);
        hi[12] = pack_h2(n4, n5);
        hi[13] = pack_h2(n6, 1.0f);     // k=27 constant 1 -> B carries BN shift
        hi[14] = hi[15] = 0u;

        uint8_t* rowA = &Amat[warp][r * ASTR];
        const int sw = (r >> 1) & 3;
        #pragma unroll
        for (int jj = 0; jj < 4; ++jj) {
            const int j = jj ^ sw;
            *(uint4*)(rowA + (j << 4)) = make_uint4(hi[4*jj], hi[4*jj+1], hi[4*jj+2], hi[4*jj+3]);
        }
    }
    __syncthreads();   // A tiles visible

    const int vsel = g >> 2;   // tile-4 voxel owned by acc4[.][0..1]; [2..3] -> vsel+2

    // per-lane ldmatrix addressing (row r = tilebase + (lane&15), chunk j0 / j0+2)
    const int lrow = lane & 15;
    const int lj0  = lane >> 4;            // 0 or 1
    const int lsw  = (lrow >> 1) & 3;      // note: tilebase is even*16 so (r>>1)&3 == ((tb+lrow)>>1)&3 iff tb%8==0; tb in {0,16,32,48,64} all %8==0 ✓

    // ---- two 32-column halves ----
    #pragma unroll 1
    for (int h = 0; h < 2; ++h) {
        // B fragments from precomputed table (L1-hot broadcast), single fp16
        uint32_t BH[16];
        {
            const uint4* bt = (const uint4*)&g_Btab[(h * 32 + lane) * 16];
            #pragma unroll
            for (int i = 0; i < 4; ++i) {
                const uint4 q = bt[i];
                BH[4*i] = q.x; BH[4*i+1] = q.y; BH[4*i+2] = q.z; BH[4*i+3] = q.w;
            }
        }
        #define BHF(nt, ks) (&BH[((nt) * 2 + (ks)) * 2])

        // tile 4 first (leftover points p=16..19 of all 4 voxels), hold acc4
        float acc4[4][4];
        {
            uint32_t a4[2][4];
            const uint32_t rb = aB + (uint32_t)((64 + lrow) * ASTR);
            ldmat4(a4[0], rb + (uint32_t)(((lj0    ) ^ lsw) << 4));
            ldmat4(a4[1], rb + (uint32_t)(((lj0 + 2) ^ lsw) << 4));
            #pragma unroll
            for (int nt = 0; nt < 4; ++nt) {
                mma16816_zc(acc4[nt], a4[0], BHF(nt, 0));   // ks=0, zero C
                mma16816  (acc4[nt], a4[1], BHF(nt, 1));    // ks=1, accumulate
            }
        }

        // per-voxel tiles + lean shuffle-max epilogue
        #pragma unroll
        for (int vi = 0; vi < VPW; ++vi) {
            uint32_t af[2][4];
            const uint32_t rb = aB + (uint32_t)((vi * 16 + lrow) * ASTR);
            ldmat4(af[0], rb + (uint32_t)(((lj0    ) ^ lsw) << 4));
            ldmat4(af[1], rb + (uint32_t)(((lj0 + 2) ^ lsw) << 4));
            float acc[4][4];
            #pragma unroll
            for (int nt = 0; nt < 4; ++nt) {
                mma16816_zc(acc[nt], af[0], BHF(nt, 0));
                mma16816  (acc[nt], af[1], BHF(nt, 1));
            }

            // per-lane max over this voxel's rows (p 0..15), merge tile-4 rows
            float pmx[8];
            #pragma unroll
            for (int nt = 0; nt < 4; ++nt) {
                pmx[2*nt]   = fmaxf(acc[nt][0], acc[nt][2]);
                pmx[2*nt+1] = fmaxf(acc[nt][1], acc[nt][3]);
            }
            if (vsel == vi) {
                #pragma unroll
                for (int nt = 0; nt < 4; ++nt) {
                    pmx[2*nt]   = fmaxf(pmx[2*nt],   acc4[nt][0]);
                    pmx[2*nt+1] = fmaxf(pmx[2*nt+1], acc4[nt][1]);
                }
            }
            if (vsel == vi - 2) {
                #pragma unroll
                for (int nt = 0; nt < 4; ++nt) {
                    pmx[2*nt]   = fmaxf(pmx[2*nt],   acc4[nt][2]);
                    pmx[2*nt+1] = fmaxf(pmx[2*nt+1], acc4[nt][3]);
                }
            }

            // lean butterfly: drop half the values each round
            const bool b4 = (lane & 16) != 0;
            float q[4];
            #pragma unroll
            for (int i = 0; i < 4; ++i) {
                const float send = b4 ? pmx[i] : pmx[4 + i];
                const float recv = __shfl_xor_sync(0xffffffffu, send, 16);
                q[i] = fmaxf(b4 ? pmx[4 + i] : pmx[i], recv);
            }
            const bool b3 = (lane & 8) != 0;
            float r2v[2];
            #pragma unroll
            for (int i = 0; i < 2; ++i) {
                const float send = b3 ? q[i] : q[2 + i];
                const float recv = __shfl_xor_sync(0xffffffffu, send, 8);
                r2v[i] = fmaxf(b3 ? q[2 + i] : q[i], recv);
            }
            const float f0 = fmaxf(r2v[0], __shfl_xor_sync(0xffffffffu, r2v[0], 4));
            const float f1 = fmaxf(r2v[1], __shfl_xor_sync(0xffffffffu, r2v[1], 4));

            // lanes with bit2==0 store cols ntp*8 + 2*t4 (+1); shift already in dot
            const int vv = v0 + vi;
            if ((lane & 4) == 0 && vv < V) {
                const int ntp = (((lane >> 4) & 1) << 1) | ((lane >> 3) & 1);
                const int col = h * 32 + ntp * 8 + 2 * t4;
                float2 r2;
                r2.x = fmaxf(0.0f, f0);
                r2.y = fmaxf(0.0f, f1);
                *(float2*)&out[(size_t)vv * 64 + col] = r2;
            }
        }
        #undef BHF
    }
}

extern "C" void kernel_launch(void* const* d_in, const int* in_sizes, int n_in,
                              void* d_out, int out_size) {
    const float4* feats4     = (const float4*)d_in[0];
    const int*    num_points = (const int*)   d_in[1];
    const float*  W          = (const float*) d_in[3];
    const float*  gamma_     = (const float*) d_in[4];
    const float*  beta_      = (const float*) d_in[5];
    const float*  rmean      = (const float*) d_in[6];
    const float*  rvar       = (const float*) d_in[7];
    float* out = (float*)d_out;

    const int V = in_sizes[1];
    lef_prep<<<1, 64>>>(W, gamma_, beta_, rmean, rvar);
    const int vox_per_cta = WARPS * VPW;
    const int grid = (V + vox_per_cta - 1) / vox_per_cta;
    lef_mma11_kernel<<<grid, THREADS>>>(feats4, num_points, out, V);
}

// round 16
// speedup vs baseline: 1.8384x; 1.0172x over previous
#include <cuda_runtime.h>
#include <cuda_fp16.h>
#include <stdint.h>

#define PP 20
#define VPW 4          // voxels per warp
#define WARPS 2
#define THREADS 64
#define ROWS 80        // A rows per warp = 5 m16 tiles
#define ASTR 64        // bytes per A row (32 fp16, XOR-swizzled chunks, no pad)

// precomputed by lef_prep: B fragments (BN-scale folded, permuted, single fp16)
// channel 27 carries the BN shift (x[27] == 1.0 in every row)
__device__ uint32_t g_Btab[2 * 32 * 16];

__device__ __forceinline__ uint32_t smem_u32(const void* p) {
    uint32_t a;
    asm("{ .reg .u64 t; cvta.to.shared.u64 t, %1; cvt.u32.u64 %0, t; }" : "=r"(a) : "l"(p));
    return a;
}
__device__ __forceinline__ float sqrt_apx(float x) {
    float r; asm("sqrt.approx.f32 %0,%1;" : "=f"(r) : "f"(x)); return r;
}
__device__ __forceinline__ uint32_t pack_h2(float x, float y) {
    __half2 t = __floats2half2_rn(x, y);
    return *(uint32_t*)&t;
}
__device__ __forceinline__ uint32_t hmul2u(uint32_t a, uint32_t b) {
    __half2 r = __hmul2(*(__half2*)&a, *(__half2*)&b);
    return *(uint32_t*)&r;
}
__device__ __forceinline__ void ldmat4(uint32_t* r, uint32_t addr) {
    asm volatile("ldmatrix.sync.aligned.m8n8.x4.shared.b16 {%0,%1,%2,%3}, [%4];"
        : "=r"(r[0]), "=r"(r[1]), "=r"(r[2]), "=r"(r[3]) : "r"(addr));
}
__device__ __forceinline__ void mma16816(float* c, const uint32_t* a, const uint32_t* b) {
    asm volatile("mma.sync.aligned.m16n8k16.row.col.f32.f16.f16.f32 "
        "{%0,%1,%2,%3},{%4,%5,%6,%7},{%8,%9},{%0,%1,%2,%3};"
        : "+f"(c[0]), "+f"(c[1]), "+f"(c[2]), "+f"(c[3])
        : "r"(a[0]), "r"(a[1]), "r"(a[2]), "r"(a[3]), "r"(b[0]), "r"(b[1]));
}
__device__ __forceinline__ void mma16816_zc(float* d, const uint32_t* a, const uint32_t* b) {
    asm volatile("mma.sync.aligned.m16n8k16.row.col.f32.f16.f16.f32 "
        "{%0,%1,%2,%3},{%4,%5,%6,%7},{%8,%9},{%10,%10,%10,%10};"
        : "=f"(d[0]), "=f"(d[1]), "=f"(d[2]), "=f"(d[3])
        : "r"(a[0]), "r"(a[1]), "r"(a[2]), "r"(a[3]), "r"(b[0]), "r"(b[1]),
          "f"(0.0f));
}
// permuted W lookup: k<20 -> dist weight row 7+k ; 20..26 -> node row k-20 ; else 0
__device__ __forceinline__ float wval(const float* __restrict__ W, int k, int n) {
    if (k < 20) return W[(7 + k) * 64 + n];
    if (k < 27) return W[(k - 20) * 64 + n];
    return 0.0f;
}
// masked distance pair: (dist(a,b0), dist(a,b1)) * qm
__device__ __forceinline__ uint32_t dpair(const float4 a, const float4 b0, const float4 b1,
                                          uint32_t qm) {
    const float dx0 = a.x - b0.x, dy0 = a.y - b0.y, dz0 = a.z - b0.z;
    const float dx1 = a.x - b1.x, dy1 = a.y - b1.y, dz1 = a.z - b1.z;
    float d20 = dx0 * dx0; d20 = fmaf(dy0, dy0, d20); d20 = fmaf(dz0, dz0, d20);
    float d21 = dx1 * dx1; d21 = fmaf(dy1, dy1, d21); d21 = fmaf(dz1, dz1, d21);
    return hmul2u(pack_h2(sqrt_apx(d20), sqrt_apx(d21)), qm);
}

// ---- pre-kernel: build B fragment table (single fp16, scale-folded, shift@27) ----
__global__ void lef_prep(const float* __restrict__ W, const float* __restrict__ gamma_,
                         const float* __restrict__ beta_, const float* __restrict__ rmean,
                         const float* __restrict__ rvar)
{
    const int t = threadIdx.x;                    // 64 threads
    const int h = t >> 5, lane = t & 31, t4 = lane & 3, gg = lane >> 2;
    uint32_t vals[16];
    #pragma unroll
    for (int nt = 0; nt < 4; ++nt) {
        const int nn = h * 32 + nt * 8 + gg;
        const float s = gamma_[nn] * rsqrtf(rvar[nn] + 1e-3f);
        const float shift = beta_[nn] - rmean[nn] * s;
        #pragma unroll
        for (int ks = 0; ks < 2; ++ks) {
            const int k0 = ks * 16 + 2 * t4;
            const int kk[4] = { k0, k0 + 1, k0 + 8, k0 + 9 };
            float wv[4];
            #pragma unroll
            for (int i = 0; i < 4; ++i) {
                const int k = kk[i];
                wv[i] = (k == 27) ? shift : wval(W, k, nn) * s;
            }
            vals[(nt * 2 + ks) * 2 + 0] = pack_h2(wv[0], wv[1]);
            vals[(nt * 2 + ks) * 2 + 1] = pack_h2(wv[2], wv[3]);
        }
    }
    uint32_t* dst = &g_Btab[(h * 32 + lane) * 16];
    #pragma unroll
    for (int i = 0; i < 16; ++i) dst[i] = vals[i];
}

__global__ void __launch_bounds__(THREADS, 15) lef_mma12_kernel(
    const float4* __restrict__ feats4,
    const int*    __restrict__ num_points,
    float* __restrict__ out,
    int V)
{
    __shared__ __align__(16) uint8_t Amat[WARPS][ROWS * ASTR];   // fp16, swizzled chunks
    __shared__ float4 cs4s[WARPS * VPW][PP];
    __shared__ float  meanv[WARPS * VPW][3];
    __shared__ int    npvs[WARPS * VPW];
    __shared__ __align__(16) uint32_t qm2s[WARPS * VPW][12];     // q<np half2 masks (10 used)

    const int tid  = threadIdx.x;
    const int warp = tid >> 5;
    const int lane = tid & 31;
    const int t4 = lane & 3, g = lane >> 2;

    // ---- stage features (coalesced LDG.128) ----
    const int v0 = (blockIdx.x * WARPS + warp) * VPW;
    for (int t = lane; t < VPW * PP; t += 32) {
        const int vi = t / PP, p = t - vi * PP;
        const int vv = v0 + vi;
        float4 f = make_float4(0.f, 0.f, 0.f, 0.f);
        if (vv < V) f = feats4[(size_t)v0 * PP + t];
        cs4s[warp * VPW + vi][p] = f;
    }
    if (lane < VPW) {
        const int vv = v0 + lane;
        npvs[warp * VPW + lane] = (vv < V) ? num_points[vv] : 1;
    }
    __syncwarp();

    // ---- per-voxel means + q-mask tables ----
    if (lane < 12) {
        const int vi = lane / 3, d = lane - vi * 3;
        const int sv = warp * VPW + vi;
        const float* c = (const float*)&cs4s[sv][0];
        float s = 0.0f;
        #pragma unroll
        for (int p = 0; p < PP; ++p) s += c[p * 4 + d];
        meanv[sv][d] = s / (float)npvs[sv];
    }
    for (int t = lane; t < VPW * 12; t += 32) {
        const int vi = t / 12, jj = t - vi * 12;
        const int sv = warp * VPW + vi;
        const int np = npvs[sv];
        const float q0m = (2 * jj     < np) ? 1.0f : 0.0f;
        const float q1m = (2 * jj + 1 < np) ? 1.0f : 0.0f;
        qm2s[sv][jj] = (jj < 10) ? pack_h2(q0m, q1m) : 0u;
    }
    __syncwarp();

    // ---- assemble A rows: lane owns voxel (lane>>3), points sub, sub+8, sub+16 ----
    // Amat row index: p<16 -> vsub*16+p ; p>=16 -> 64 + vsub*4 + (p-16)
    // chunk j of row r stored at r*64 + ((j ^ ((r>>1)&3)) << 4)  -- conflict-free
    {
        const int sub  = lane & 7;
        const int vsub = lane >> 3;
        const int sv   = warp * VPW + vsub;
        const bool has2 = (sub < 4);
        const float4 A0 = cs4s[sv][sub];
        const float4 A1 = cs4s[sv][sub + 8];
        const float4 A2 = has2 ? cs4s[sv][sub + 16] : make_float4(0.f, 0.f, 0.f, 0.f);
        const int   np  = npvs[sv];
        const float m0 = meanv[sv][0], m1 = meanv[sv][1], m2 = meanv[sv][2];

        // q-mask multipliers for this voxel (loaded ONCE)
        const uint4 qa = *(const uint4*)&qm2s[sv][0];
        const uint4 qb = *(const uint4*)&qm2s[sv][4];
        const uint2 qc = *(const uint2*)&qm2s[sv][8];
        const uint32_t qm[10] = { qa.x, qa.y, qa.z, qa.w, qb.x, qb.y, qb.z, qb.w, qc.x, qc.y };

        const int r0 = vsub * 16 + sub, r1 = r0 + 8, r2 = 64 + vsub * 4 + sub;
        uint8_t* R0 = &Amat[warp][r0 * ASTR];
        uint8_t* R1 = &Amat[warp][r1 * ASTR];
        uint8_t* R2 = &Amat[warp][r2 * ASTR];
        const int s0 = (r0 >> 1) & 3, s1 = (r1 >> 1) & 3, s2 = (r2 >> 1) & 3;

        // chunks 0,1: distance pairs q0..7, q8..15 (b-loads shared across rows)
        #pragma unroll
        for (int ch = 0; ch < 2; ++ch) {
            uint32_t h0[4], h1[4], h2[4];
            #pragma unroll
            for (int i = 0; i < 4; ++i) {
                const int jj = ch * 4 + i;
                const float4 b0 = cs4s[sv][2 * jj], b1 = cs4s[sv][2 * jj + 1];
                h0[i] = dpair(A0, b0, b1, qm[jj]);
                h1[i] = dpair(A1, b0, b1, qm[jj]);
                h2[i] = dpair(A2, b0, b1, qm[jj]);
            }
            *(uint4*)(R0 + ((ch ^ s0) << 4)) = make_uint4(h0[0], h0[1], h0[2], h0[3]);
            *(uint4*)(R1 + ((ch ^ s1) << 4)) = make_uint4(h1[0], h1[1], h1[2], h1[3]);
            if (has2)
                *(uint4*)(R2 + ((ch ^ s2) << 4)) = make_uint4(h2[0], h2[1], h2[2], h2[3]);
        }
        // chunk 2: q16..19 + node n0..n3 ;  chunk 3: n4,n5,n6,one,0...
        {
            const float4 b16 = cs4s[sv][16], b17 = cs4s[sv][17];
            const float4 b18 = cs4s[sv][18], b19 = cs4s[sv][19];
            #pragma unroll
            for (int rr = 0; rr < 3; ++rr) {
                const float4 a = (rr == 0) ? A0 : (rr == 1) ? A1 : A2;
                const int   p = (rr == 0) ? sub : (rr == 1) ? sub + 8 : sub + 16;
                if (rr == 2 && !has2) break;
                const float pm = (p < np) ? 1.0f : 0.0f;
                uint32_t h[4];
                h[0] = dpair(a, b16, b17, qm[8]);
                h[1] = dpair(a, b18, b19, qm[9]);
                h[2] = pack_h2(a.x * pm, a.y * pm);
                h[3] = pack_h2(a.z * pm, a.w * pm);
                uint8_t* R = (rr == 0) ? R0 : (rr == 1) ? R1 : R2;
                const int s = (rr == 0) ? s0 : (rr == 1) ? s1 : s2;
                *(uint4*)(R + ((2 ^ s) << 4)) = make_uint4(h[0], h[1], h[2], h[3]);
                const uint32_t g0 = pack_h2((a.x - m0) * pm, (a.y - m1) * pm);
                const uint32_t g1 = pack_h2((a.z - m2) * pm, 1.0f);  // k=27 const 1
                *(uint4*)(R + ((3 ^ s) << 4)) = make_uint4(g0, g1, 0u, 0u);
            }
        }
    }
    __syncthreads();   // A tiles visible

    const uint32_t aB = smem_u32(&Amat[warp][0]);
    const int vsel = g >> 2;   // tile-4 voxel owned by acc4[.][0..1]; [2..3] -> vsel+2

    // per-lane ldmatrix addressing (row r = tilebase + (lane&15), chunk j0 / j0+2)
    const int lrow = lane & 15;
    const int lj0  = lane >> 4;            // 0 or 1
    const int lsw  = (lrow >> 1) & 3;      // tilebases all %8==0 so swizzle consistent

    // ---- two 32-column halves ----
    #pragma unroll 1
    for (int h = 0; h < 2; ++h) {
        uint32_t BH[16];
        {
            const uint4* bt = (const uint4*)&g_Btab[(h * 32 + lane) * 16];
            #pragma unroll
            for (int i = 0; i < 4; ++i) {
                const uint4 q = bt[i];
                BH[4*i] = q.x; BH[4*i+1] = q.y; BH[4*i+2] = q.z; BH[4*i+3] = q.w;
            }
        }
        #define BHF(nt, ks) (&BH[((nt) * 2 + (ks)) * 2])

        // tile 4 first (leftover points p=16..19 of all 4 voxels), hold acc4
        float acc4[4][4];
        {
            uint32_t a4[2][4];
            const uint32_t rb = aB + (uint32_t)((64 + lrow) * ASTR);
            ldmat4(a4[0], rb + (uint32_t)(((lj0    ) ^ lsw) << 4));
            ldmat4(a4[1], rb + (uint32_t)(((lj0 + 2) ^ lsw) << 4));
            #pragma unroll
            for (int nt = 0; nt < 4; ++nt) {
                mma16816_zc(acc4[nt], a4[0], BHF(nt, 0));
                mma16816  (acc4[nt], a4[1], BHF(nt, 1));
            }
        }

        // per-voxel tiles + lean shuffle-max epilogue
        #pragma unroll
        for (int vi = 0; vi < VPW; ++vi) {
            uint32_t af[2][4];
            const uint32_t rb = aB + (uint32_t)((vi * 16 + lrow) * ASTR);
            ldmat4(af[0], rb + (uint32_t)(((lj0    ) ^ lsw) << 4));
            ldmat4(af[1], rb + (uint32_t)(((lj0 + 2) ^ lsw) << 4));
            float acc[4][4];
            #pragma unroll
            for (int nt = 0; nt < 4; ++nt) {
                mma16816_zc(acc[nt], af[0], BHF(nt, 0));
                mma16816  (acc[nt], af[1], BHF(nt, 1));
            }

            float pmx[8];
            #pragma unroll
            for (int nt = 0; nt < 4; ++nt) {
                pmx[2*nt]   = fmaxf(acc[nt][0], acc[nt][2]);
                pmx[2*nt+1] = fmaxf(acc[nt][1], acc[nt][3]);
            }
            if (vsel == vi) {
                #pragma unroll
                for (int nt = 0; nt < 4; ++nt) {
                    pmx[2*nt]   = fmaxf(pmx[2*nt],   acc4[nt][0]);
                    pmx[2*nt+1] = fmaxf(pmx[2*nt+1], acc4[nt][1]);
                }
            }
            if (vsel == vi - 2) {
                #pragma unroll
                for (int nt = 0; nt < 4; ++nt) {
                    pmx[2*nt]   = fmaxf(pmx[2*nt],   acc4[nt][2]);
                    pmx[2*nt+1] = fmaxf(pmx[2*nt+1], acc4[nt][3]);
                }
            }

            // lean butterfly: drop half the values each round
            const bool b4 = (lane & 16) != 0;
            float q[4];
            #pragma unroll
            for (int i = 0; i < 4; ++i) {
                const float send = b4 ? pmx[i] : pmx[4 + i];
                const float recv = __shfl_xor_sync(0xffffffffu, send, 16);
                q[i] = fmaxf(b4 ? pmx[4 + i] : pmx[i], recv);
            }
            const bool b3 = (lane & 8) != 0;
            float r2v[2];
            #pragma unroll
            for (int i = 0; i < 2; ++i) {
                const float send = b3 ? q[i] : q[2 + i];
                const float recv = __shfl_xor_sync(0xffffffffu, send, 8);
                r2v[i] = fmaxf(b3 ? q[2 + i] : q[i], recv);
            }
            const float f0 = fmaxf(r2v[0], __shfl_xor_sync(0xffffffffu, r2v[0], 4));
            const float f1 = fmaxf(r2v[1], __shfl_xor_sync(0xffffffffu, r2v[1], 4));

            const int vv = v0 + vi;
            if ((lane & 4) == 0 && vv < V) {
                const int ntp = (((lane >> 4) & 1) << 1) | ((lane >> 3) & 1);
                const int col = h * 32 + ntp * 8 + 2 * t4;
                float2 r2;
                r2.x = fmaxf(0.0f, f0);
                r2.y = fmaxf(0.0f, f1);
                *(float2*)&out[(size_t)vv * 64 + col] = r2;
            }
        }
        #undef BHF
    }
}

extern "C" void kernel_launch(void* const* d_in, const int* in_sizes, int n_in,
                              void* d_out, int out_size) {
    const float4* feats4     = (const float4*)d_in[0];
    const int*    num_points = (const int*)   d_in[1];
    const float*  W          = (const float*) d_in[3];
    const float*  gamma_     = (const float*) d_in[4];
    const float*  beta_      = (const float*) d_in[5];
    const float*  rmean      = (const float*) d_in[6];
    const float*  rvar       = (const float*) d_in[7];
    float* out = (float*)d_out;

    const int V = in_sizes[1];
    lef_prep<<<1, 64>>>(W, gamma_, beta_, rmean, rvar);
    const int vox_per_cta = WARPS * VPW;
    const int grid = (V + vox_per_cta - 1) / vox_per_cta;
    lef_mma12_kernel<<<grid, THREADS>>>(feats4, num_points, out, V);
}

// round 17
// speedup vs baseline: 1.9019x; 1.0346x over previous
#include <cuda_runtime.h>
#include <cuda_fp16.h>
#include <stdint.h>

#define PP 20
#define VPW 4          // voxels per warp
#define WARPS 2
#define THREADS 64
#define ROWS 80        // A rows per warp = 5 m16 tiles
#define ASTR 64        // bytes per A row (32 fp16, XOR-swizzled chunks, no pad)

// precomputed by lef_prep: B fragments (BN-scale folded, permuted, single fp16)
// channel 27 carries the BN shift (x[27] == 1.0 in every row)
__device__ uint32_t g_Btab[2 * 32 * 16];

__device__ __forceinline__ uint32_t smem_u32(const void* p) {
    uint32_t a;
    asm("{ .reg .u64 t; cvta.to.shared.u64 t, %1; cvt.u32.u64 %0, t; }" : "=r"(a) : "l"(p));
    return a;
}
__device__ __forceinline__ float sqrt_apx(float x) {
    float r; asm("sqrt.approx.f32 %0,%1;" : "=f"(r) : "f"(x)); return r;
}
__device__ __forceinline__ uint32_t pack_h2(float x, float y) {
    __half2 t = __floats2half2_rn(x, y);
    return *(uint32_t*)&t;
}
__device__ __forceinline__ uint32_t hmul2u(uint32_t a, uint32_t b) {
    __half2 r = __hmul2(*(__half2*)&a, *(__half2*)&b);
    return *(uint32_t*)&r;
}
__device__ __forceinline__ void ldmat4(uint32_t* r, uint32_t addr) {
    asm volatile("ldmatrix.sync.aligned.m8n8.x4.shared.b16 {%0,%1,%2,%3}, [%4];"
        : "=r"(r[0]), "=r"(r[1]), "=r"(r[2]), "=r"(r[3]) : "r"(addr));
}
__device__ __forceinline__ void mma16816(float* c, const uint32_t* a, const uint32_t* b) {
    asm volatile("mma.sync.aligned.m16n8k16.row.col.f32.f16.f16.f32 "
        "{%0,%1,%2,%3},{%4,%5,%6,%7},{%8,%9},{%0,%1,%2,%3};"
        : "+f"(c[0]), "+f"(c[1]), "+f"(c[2]), "+f"(c[3])
        : "r"(a[0]), "r"(a[1]), "r"(a[2]), "r"(a[3]), "r"(b[0]), "r"(b[1]));
}
__device__ __forceinline__ void mma16816_zc(float* d, const uint32_t* a, const uint32_t* b) {
    asm volatile("mma.sync.aligned.m16n8k16.row.col.f32.f16.f16.f32 "
        "{%0,%1,%2,%3},{%4,%5,%6,%7},{%8,%9},{%10,%10,%10,%10};"
        : "=f"(d[0]), "=f"(d[1]), "=f"(d[2]), "=f"(d[3])
        : "r"(a[0]), "r"(a[1]), "r"(a[2]), "r"(a[3]), "r"(b[0]), "r"(b[1]),
          "f"(0.0f));
}
// permuted W lookup: k<20 -> dist weight row 7+k ; 20..26 -> node row k-20 ; else 0
__device__ __forceinline__ float wval(const float* __restrict__ W, int k, int n) {
    if (k < 20) return W[(7 + k) * 64 + n];
    if (k < 27) return W[(k - 20) * 64 + n];
    return 0.0f;
}
// masked distance pair: (dist(a,b0), dist(a,b1)) * qm
__device__ __forceinline__ uint32_t dpair(const float4 a, const float4 b0, const float4 b1,
                                          uint32_t qm) {
    const float dx0 = a.x - b0.x, dy0 = a.y - b0.y, dz0 = a.z - b0.z;
    const float dx1 = a.x - b1.x, dy1 = a.y - b1.y, dz1 = a.z - b1.z;
    float d20 = dx0 * dx0; d20 = fmaf(dy0, dy0, d20); d20 = fmaf(dz0, dz0, d20);
    float d21 = dx1 * dx1; d21 = fmaf(dy1, dy1, d21); d21 = fmaf(dz1, dz1, d21);
    return hmul2u(pack_h2(sqrt_apx(d20), sqrt_apx(d21)), qm);
}

// ---- pre-kernel: build B fragment table (single fp16, scale-folded, shift@27) ----
__global__ void lef_prep(const float* __restrict__ W, const float* __restrict__ gamma_,
                         const float* __restrict__ beta_, const float* __restrict__ rmean,
                         const float* __restrict__ rvar)
{
    const int t = threadIdx.x;                    // 64 threads
    const int h = t >> 5, lane = t & 31, t4 = lane & 3, gg = lane >> 2;
    uint32_t vals[16];
    #pragma unroll
    for (int nt = 0; nt < 4; ++nt) {
        const int nn = h * 32 + nt * 8 + gg;
        const float s = gamma_[nn] * rsqrtf(rvar[nn] + 1e-3f);
        const float shift = beta_[nn] - rmean[nn] * s;
        #pragma unroll
        for (int ks = 0; ks < 2; ++ks) {
            const int k0 = ks * 16 + 2 * t4;
            const int kk[4] = { k0, k0 + 1, k0 + 8, k0 + 9 };
            float wv[4];
            #pragma unroll
            for (int i = 0; i < 4; ++i) {
                const int k = kk[i];
                wv[i] = (k == 27) ? shift : wval(W, k, nn) * s;
            }
            vals[(nt * 2 + ks) * 2 + 0] = pack_h2(wv[0], wv[1]);
            vals[(nt * 2 + ks) * 2 + 1] = pack_h2(wv[2], wv[3]);
        }
    }
    uint32_t* dst = &g_Btab[(h * 32 + lane) * 16];
    #pragma unroll
    for (int i = 0; i < 16; ++i) dst[i] = vals[i];
}

__global__ void __launch_bounds__(THREADS, 16) lef_mma13_kernel(
    const float4* __restrict__ feats4,
    const int*    __restrict__ num_points,
    float* __restrict__ out,
    int V)
{
    __shared__ __align__(16) uint8_t Amat[WARPS][ROWS * ASTR];   // fp16, swizzled chunks
    __shared__ float4 cs4s[WARPS * VPW][PP];
    __shared__ float  meanv[WARPS * VPW][3];
    __shared__ int    npvs[WARPS * VPW];
    __shared__ __align__(16) uint32_t qm2s[WARPS * VPW][12];     // q<np half2 masks (10 used)

    const int tid  = threadIdx.x;
    const int warp = tid >> 5;
    const int lane = tid & 31;
    const int t4 = lane & 3, g = lane >> 2;

    // ---- stage features (coalesced LDG.128) ----
    const int v0 = (blockIdx.x * WARPS + warp) * VPW;
    for (int t = lane; t < VPW * PP; t += 32) {
        const int vi = t / PP, p = t - vi * PP;
        const int vv = v0 + vi;
        float4 f = make_float4(0.f, 0.f, 0.f, 0.f);
        if (vv < V) f = feats4[(size_t)v0 * PP + t];
        cs4s[warp * VPW + vi][p] = f;
    }
    if (lane < VPW) {
        const int vv = v0 + lane;
        npvs[warp * VPW + lane] = (vv < V) ? num_points[vv] : 1;
    }
    __syncwarp();

    // ---- per-voxel means + q-mask tables ----
    if (lane < 12) {
        const int vi = lane / 3, d = lane - vi * 3;
        const int sv = warp * VPW + vi;
        const float* c = (const float*)&cs4s[sv][0];
        float s = 0.0f;
        #pragma unroll
        for (int p = 0; p < PP; ++p) s += c[p * 4 + d];
        meanv[sv][d] = s / (float)npvs[sv];
    }
    for (int t = lane; t < VPW * 12; t += 32) {
        const int vi = t / 12, jj = t - vi * 12;
        const int sv = warp * VPW + vi;
        const int np = npvs[sv];
        const float q0m = (2 * jj     < np) ? 1.0f : 0.0f;
        const float q1m = (2 * jj + 1 < np) ? 1.0f : 0.0f;
        qm2s[sv][jj] = (jj < 10) ? pack_h2(q0m, q1m) : 0u;
    }
    __syncwarp();

    // ---- assemble A rows: lane owns voxel (lane>>3), points sub, sub+8, sub+16 ----
    // Amat row index: p<16 -> vsub*16+p ; p>=16 -> 64 + vsub*4 + (p-16)
    // chunk j of row r stored at r*64 + ((j ^ ((r>>1)&3)) << 4)  -- conflict-free
    {
        const int sub  = lane & 7;
        const int vsub = lane >> 3;
        const int sv   = warp * VPW + vsub;
        const bool has2 = (sub < 4);
        const float4 A0 = cs4s[sv][sub];
        const float4 A1 = cs4s[sv][sub + 8];
        const float4 A2 = has2 ? cs4s[sv][sub + 16] : make_float4(0.f, 0.f, 0.f, 0.f);
        const int   np  = npvs[sv];
        const float m0 = meanv[sv][0], m1 = meanv[sv][1], m2 = meanv[sv][2];

        // q-mask multipliers for this voxel (loaded ONCE)
        const uint4 qa = *(const uint4*)&qm2s[sv][0];
        const uint4 qb = *(const uint4*)&qm2s[sv][4];
        const uint2 qc = *(const uint2*)&qm2s[sv][8];
        const uint32_t qm[10] = { qa.x, qa.y, qa.z, qa.w, qb.x, qb.y, qb.z, qb.w, qc.x, qc.y };

        const int r0 = vsub * 16 + sub, r1 = r0 + 8, r2 = 64 + vsub * 4 + sub;
        uint8_t* R0 = &Amat[warp][r0 * ASTR];
        uint8_t* R1 = &Amat[warp][r1 * ASTR];
        uint8_t* R2 = &Amat[warp][r2 * ASTR];
        const int s0 = (r0 >> 1) & 3, s1 = (r1 >> 1) & 3, s2 = (r2 >> 1) & 3;

        // chunks 0,1: distance pairs q0..7, q8..15 (b-loads shared across rows)
        #pragma unroll
        for (int ch = 0; ch < 2; ++ch) {
            uint32_t h0[4], h1[4], h2[4];
            #pragma unroll
            for (int i = 0; i < 4; ++i) {
                const int jj = ch * 4 + i;
                const float4 b0 = cs4s[sv][2 * jj], b1 = cs4s[sv][2 * jj + 1];
                h0[i] = dpair(A0, b0, b1, qm[jj]);
                h1[i] = dpair(A1, b0, b1, qm[jj]);
                h2[i] = dpair(A2, b0, b1, qm[jj]);
            }
            *(uint4*)(R0 + ((ch ^ s0) << 4)) = make_uint4(h0[0], h0[1], h0[2], h0[3]);
            *(uint4*)(R1 + ((ch ^ s1) << 4)) = make_uint4(h1[0], h1[1], h1[2], h1[3]);
            if (has2)
                *(uint4*)(R2 + ((ch ^ s2) << 4)) = make_uint4(h2[0], h2[1], h2[2], h2[3]);
        }
        // chunk 2: q16..19 + node n0..n3 ;  chunk 3: n4,n5,n6,one,0...
        {
            const float4 b16 = cs4s[sv][16], b17 = cs4s[sv][17];
            const float4 b18 = cs4s[sv][18], b19 = cs4s[sv][19];
            #pragma unroll
            for (int rr = 0; rr < 3; ++rr) {
                const float4 a = (rr == 0) ? A0 : (rr == 1) ? A1 : A2;
                const int   p = (rr == 0) ? sub : (rr == 1) ? sub + 8 : sub + 16;
                if (rr == 2 && !has2) break;
                const float pm = (p < np) ? 1.0f : 0.0f;
                uint32_t h[4];
                h[0] = dpair(a, b16, b17, qm[8]);
                h[1] = dpair(a, b18, b19, qm[9]);
                h[2] = pack_h2(a.x * pm, a.y * pm);
                h[3] = pack_h2(a.z * pm, a.w * pm);
                uint8_t* R = (rr == 0) ? R0 : (rr == 1) ? R1 : R2;
                const int s = (rr == 0) ? s0 : (rr == 1) ? s1 : s2;
                *(uint4*)(R + ((2 ^ s) << 4)) = make_uint4(h[0], h[1], h[2], h[3]);
                const uint32_t g0 = pack_h2((a.x - m0) * pm, (a.y - m1) * pm);
                const uint32_t g1 = pack_h2((a.z - m2) * pm, 1.0f);  // k=27 const 1
                *(uint4*)(R + ((3 ^ s) << 4)) = make_uint4(g0, g1, 0u, 0u);
            }
        }
    }
    __syncthreads();   // A tiles visible

    const uint32_t aB = smem_u32(&Amat[warp][0]);
    const int vsel = g >> 2;   // tile-4 voxel owned by acc4[.][0..1]; [2..3] -> vsel+2

    // per-lane ldmatrix addressing (row r = tilebase + (lane&15), chunk j0 / j0+2)
    const int lrow = lane & 15;
    const int lj0  = lane >> 4;            // 0 or 1
    const int lsw  = (lrow >> 1) & 3;      // tilebases all %8==0 so swizzle consistent

    // ---- two 32-column halves ----
    #pragma unroll 1
    for (int h = 0; h < 2; ++h) {
        uint32_t BH[16];
        {
            const uint4* bt = (const uint4*)&g_Btab[(h * 32 + lane) * 16];
            #pragma unroll
            for (int i = 0; i < 4; ++i) {
                const uint4 q = bt[i];
                BH[4*i] = q.x; BH[4*i+1] = q.y; BH[4*i+2] = q.z; BH[4*i+3] = q.w;
            }
        }
        #define BHF(nt, ks) (&BH[((nt) * 2 + (ks)) * 2])

        // tile 4 first (leftover points p=16..19 of all 4 voxels), hold acc4
        float acc4[4][4];
        {
            uint32_t a4[2][4];
            const uint32_t rb = aB + (uint32_t)((64 + lrow) * ASTR);
            ldmat4(a4[0], rb + (uint32_t)(((lj0    ) ^ lsw) << 4));
            ldmat4(a4[1], rb + (uint32_t)(((lj0 + 2) ^ lsw) << 4));
            #pragma unroll
            for (int nt = 0; nt < 4; ++nt) {
                mma16816_zc(acc4[nt], a4[0], BHF(nt, 0));
                mma16816  (acc4[nt], a4[1], BHF(nt, 1));
            }
        }

        // per-voxel tiles + lean shuffle-max epilogue
        #pragma unroll
        for (int vi = 0; vi < VPW; ++vi) {
            uint32_t af[2][4];
            const uint32_t rb = aB + (uint32_t)((vi * 16 + lrow) * ASTR);
            ldmat4(af[0], rb + (uint32_t)(((lj0    ) ^ lsw) << 4));
            ldmat4(af[1], rb + (uint32_t)(((lj0 + 2) ^ lsw) << 4));
            float acc[4][4];
            #pragma unroll
            for (int nt = 0; nt < 4; ++nt) {
                mma16816_zc(acc[nt], af[0], BHF(nt, 0));
                mma16816  (acc[nt], af[1], BHF(nt, 1));
            }

            float pmx[8];
            #pragma unroll
            for (int nt = 0; nt < 4; ++nt) {
                pmx[2*nt]   = fmaxf(acc[nt][0], acc[nt][2]);
                pmx[2*nt+1] = fmaxf(acc[nt][1], acc[nt][3]);
            }
            if (vsel == vi) {
                #pragma unroll
                for (int nt = 0; nt < 4; ++nt) {
                    pmx[2*nt]   = fmaxf(pmx[2*nt],   acc4[nt][0]);
                    pmx[2*nt+1] = fmaxf(pmx[2*nt+1], acc4[nt][1]);
                }
            }
            if (vsel == vi - 2) {
                #pragma unroll
                for (int nt = 0; nt < 4; ++nt) {
                    pmx[2*nt]   = fmaxf(pmx[2*nt],   acc4[nt][2]);
                    pmx[2*nt+1] = fmaxf(pmx[2*nt+1], acc4[nt][3]);
                }
            }

            // lean butterfly: drop half the values each round (3 dropping rounds)
            const bool b4 = (lane & 16) != 0;
            float q[4];
            #pragma unroll
            for (int i = 0; i < 4; ++i) {
                const float send = b4 ? pmx[i] : pmx[4 + i];
                const float recv = __shfl_xor_sync(0xffffffffu, send, 16);
                q[i] = fmaxf(b4 ? pmx[4 + i] : pmx[i], recv);
            }
            const bool b3 = (lane & 8) != 0;
            float r2v[2];
            #pragma unroll
            for (int i = 0; i < 2; ++i) {
                const float send = b3 ? q[i] : q[2 + i];
                const float recv = __shfl_xor_sync(0xffffffffu, send, 8);
                r2v[i] = fmaxf(b3 ? q[2 + i] : q[i], recv);
            }
            // r3: dropping by bit2 -> every lane ends with ONE fully-reduced column
            const bool b2 = (lane & 4) != 0;
            const float send3 = b2 ? r2v[0] : r2v[1];
            const float recv3 = __shfl_xor_sync(0xffffffffu, send3, 4);
            const float f = fmaxf(b2 ? r2v[1] : r2v[0], recv3);

            // all 32 lanes store one col; lane->col bijective in the 32-col half
            const int vv = v0 + vi;
            if (vv < V) {
                const int ntp = (((lane >> 4) & 1) << 1) | ((lane >> 3) & 1);
                const int col = h * 32 + ntp * 8 + 2 * t4 + ((lane >> 2) & 1);
                out[(size_t)vv * 64 + col] = fmaxf(0.0f, f);
            }
        }
        #undef BHF
    }
}

extern "C" void kernel_launch(void* const* d_in, const int* in_sizes, int n_in,
                              void* d_out, int out_size) {
    const float4* feats4     = (const float4*)d_in[0];
    const int*    num_points = (const int*)   d_in[1];
    const float*  W          = (const float*) d_in[3];
    const float*  gamma_     = (const float*) d_in[4];
    const float*  beta_      = (const float*) d_in[5];
    const float*  rmean      = (const float*) d_in[6];
    const float*  rvar       = (const float*) d_in[7];
    float* out = (float*)d_out;

    const int V = in_sizes[1];
    lef_prep<<<1, 64>>>(W, gamma_, beta_, rmean, rvar);
    const int vox_per_cta = WARPS * VPW;
    const int grid = (V + vox_per_cta - 1) / vox_per_cta;
    lef_mma13_kernel<<<grid, THREADS>>>(feats4, num_points, out, V);
}